// round 10
// baseline (speedup 1.0000x reference)
#include <cuda_runtime.h>
#include <math.h>
#include <stdint.h>

// ---------------- problem dims ----------------
constexpr int cB   = 2;
constexpr int cS   = 2048;
constexpr int cE   = 2048;
constexpr int cH   = 2688;
constexpr int c2H  = 2 * cH;
constexpr int cNH  = 4;
constexpr int cDH  = 672;
constexpr int cKS  = 4;
constexpr int cNPH = 672;
constexpr long long cBS  = (long long)cB * cS;        // 4096
constexpr long long cBSH = cBS * cH;
constexpr long long cSCORES = (long long)cB * cNH * cS * cS;
constexpr int cBHS = cB * cNH * cS;
constexpr int c3H  = 3 * cH;
constexpr int cHALF = c3H / 2;

// ---------------- device scratch ----------------
__device__ float g_xmz[cBS * (long long)c2H];
__device__ float g_xca[cBSH];
__device__ float g_q  [cBSH];
__device__ float g_k  [cBSH];
__device__ float g_v  [cBSH];
__device__ float g_h  [cBSH];
__device__ float g_hs [cBSH];
__device__ float g_scores[cSCORES];
__device__ float g_ipre[cBHS];
__device__ float g_fpre[cBHS];
__device__ float g_cs  [cBHS];
__device__ float g_a   [cBHS];
__device__ float g_pm  [cBHS];
__device__ float g_rs  [cBHS];
__device__ float g_nsum[cBHS];

// ---------------- helpers ----------------
__device__ __forceinline__ uint32_t f2tf32(float x) {
    uint32_t r;
    asm("cvt.rna.tf32.f32 %0, %1;" : "=r"(r) : "f"(x));
    return r;
}
__device__ __forceinline__ void cp16(uint32_t saddr, const void* gptr, int bytes) {
    asm volatile("cp.async.cg.shared.global [%0], [%1], 16, %2;\n"
                 :: "r"(saddr), "l"(gptr), "r"(bytes));
}
__device__ __forceinline__ void cp_commit() { asm volatile("cp.async.commit_group;\n" ::: "memory"); }
__device__ __forceinline__ void cp_wait0()  { asm volatile("cp.async.wait_group 0;\n" ::: "memory"); }

#define MMA_TF32(d, a, b)                                                      \
    asm volatile(                                                              \
        "mma.sync.aligned.m16n8k8.row.col.f32.tf32.tf32.f32 "                  \
        "{%0,%1,%2,%3},{%4,%5,%6,%7},{%8,%9},{%0,%1,%2,%3};\n"                 \
        : "+f"(d[0]), "+f"(d[1]), "+f"(d[2]), "+f"(d[3])                       \
        : "r"(a[0]), "r"(a[1]), "r"(a[2]), "r"(a[3]), "r"(b[0]), "r"(b[1]))

// ---------------- tf32 tensor-core GEMM: 256x128x16 tiles ----------------
// Raises arithmetic intensity to 42.7 FLOP/B (L2-bandwidth was the binding
// constraint at 128x128). Warp grid 4(M)x2(N), warp tile 64x64.
// mode 0: C = alpha * acc
// mode 1: scores epilogue + fused causal row sums into p3 (atomics)
// mode 2: row scale by p1[m]; K limited to tileM+BM (A lower-tri)
#define BM 256
#define BN 128
#define BK 16
#define ASTR 20    // BK + 4
#define BSTR 136   // BN + 8

// dynamic smem float offsets
constexpr int FA0 = 0;                 // A stage 0: 256*20 = 5120
constexpr int FA1 = 5120;
constexpr int FB0 = 10240;             // B stage:  max(128*20, 16*136)=2560
constexpr int FB1 = 12800;
constexpr int SMEMSZ = 15360 * 4;      // 61440 bytes

__global__ __launch_bounds__(256)
void tgemm_kernel(int M, int N, int K,
                  const float* __restrict__ A, int lda, long long sAb, long long sAn,
                  const float* __restrict__ B, int ldb, long long sBb, long long sBn,
                  float* __restrict__ C, int ldc, long long sCb, long long sCn,
                  int nhd, int transB, int mode, float alpha,
                  const float* __restrict__ p1, const float* __restrict__ p2,
                  float* __restrict__ p3, int pstr)
{
    const int z  = blockIdx.z;
    const int zb = z / nhd, zn = z % nhd;
    A += zb * sAb + zn * sAn;
    B += zb * sBb + zn * sBn;
    C += zb * sCb + zn * sCn;

    const int tileM = blockIdx.y * BM;
    const int tileN = blockIdx.x * BN;
    if (mode == 1 && tileN > tileM + BM - 1) return;   // fully masked tile

    extern __shared__ float smem[];
    float* Abuf[2] = { smem + FA0, smem + FA1 };
    float* Bbuf[2] = { smem + FB0, smem + FB1 };
    uint32_t sA[2], sB[2];
    sA[0] = (uint32_t)__cvta_generic_to_shared(Abuf[0]);
    sA[1] = (uint32_t)__cvta_generic_to_shared(Abuf[1]);
    sB[0] = (uint32_t)__cvta_generic_to_shared(Bbuf[0]);
    sB[1] = (uint32_t)__cvta_generic_to_shared(Bbuf[1]);

    const int t    = threadIdx.x;
    const int lane = t & 31;
    const int warp = t >> 5;
    const int g    = lane >> 2;     // 0..7
    const int t4   = lane & 3;      // 0..3
    const int wm   = (warp & 3) * 64;   // 4 M-warps
    const int wn   = (warp >> 2) * 64;  // 2 N-warps

    float acc[4][8][4];
#pragma unroll
    for (int i = 0; i < 4; i++)
#pragma unroll
        for (int j = 0; j < 8; j++)
#pragma unroll
            for (int r = 0; r < 4; r++) acc[i][j][r] = 0.f;

    int Kend = K;
    if (mode == 2) { int lim = tileM + BM; Kend = lim < K ? lim : K; }
    const int nIter = Kend / BK;

    auto loadTiles = [&](int stg, int k0) {
#pragma unroll
        for (int hh = 0; hh < 4; hh++) {          // A: 256 rows x 4 chunks
            int c   = t + hh * 256;
            int row = c >> 2;
            int kc  = (c & 3) * 4;
            const float* gp = &A[(long long)(tileM + row) * lda + k0 + kc];
            cp16(sA[stg] + (row * ASTR + kc) * 4, gp, 16);
        }
        if (!transB) {
#pragma unroll
            for (int hh = 0; hh < 2; hh++) {      // B: 16 x 128
                int c  = t + hh * 256;
                int kr = c >> 5;
                int n4 = (c & 31) * 4;
                int gn = tileN + n4;
                int ok = (gn < N);
                const float* gp = &B[(long long)(k0 + kr) * ldb + (ok ? gn : 0)];
                cp16(sB[stg] + (kr * BSTR + n4) * 4, gp, ok ? 16 : 0);
            }
        } else {
#pragma unroll
            for (int hh = 0; hh < 2; hh++) {      // B: 128 rows x K16
                int c   = t + hh * 256;
                int row = c >> 2;
                int kc  = (c & 3) * 4;
                const float* gp = &B[(long long)(tileN + row) * ldb + k0 + kc];
                cp16(sB[stg] + (row * ASTR + kc) * 4, gp, 16);
            }
        }
        cp_commit();
    };

    loadTiles(0, 0);
    cp_wait0();
    __syncthreads();

    for (int it = 0; it < nIter; it++) {
        const int s  = it & 1;
        const int kn = (it + 1) * BK;
        const bool more = (kn < Kend);
        if (more) loadTiles(s ^ 1, kn);

        const float* Asb = Abuf[s];
        const float* Bsb = Bbuf[s];
#pragma unroll
        for (int ks = 0; ks < BK; ks += 8) {
            uint32_t af[4][4], bf[8][2];
#pragma unroll
            for (int i = 0; i < 4; i++) {
                int m0 = wm + i * 16 + g;
                af[i][0] = f2tf32(Asb[(m0    ) * ASTR + ks + t4    ]);
                af[i][1] = f2tf32(Asb[(m0 + 8) * ASTR + ks + t4    ]);
                af[i][2] = f2tf32(Asb[(m0    ) * ASTR + ks + t4 + 4]);
                af[i][3] = f2tf32(Asb[(m0 + 8) * ASTR + ks + t4 + 4]);
            }
#pragma unroll
            for (int j = 0; j < 8; j++) {
                int n0 = wn + j * 8 + g;
                if (transB) {
                    bf[j][0] = f2tf32(Bsb[n0 * ASTR + ks + t4    ]);
                    bf[j][1] = f2tf32(Bsb[n0 * ASTR + ks + t4 + 4]);
                } else {
                    bf[j][0] = f2tf32(Bsb[(ks + t4    ) * BSTR + n0]);
                    bf[j][1] = f2tf32(Bsb[(ks + t4 + 4) * BSTR + n0]);
                }
            }
#pragma unroll
            for (int i = 0; i < 4; i++)
#pragma unroll
                for (int j = 0; j < 8; j++)
                    MMA_TF32(acc[i][j], af[i], bf[j]);
        }

        if (more) cp_wait0();
        __syncthreads();
    }

    // ---- epilogue ----
    const long long zoff = (long long)z * pstr;
    float p1v[16];
    if (mode == 1) {
#pragma unroll
        for (int j = 0; j < 8; j++) {
            int gn = tileN + wn + j * 8 + t4 * 2;
            p1v[2 * j]     = p1[zoff + gn];
            p1v[2 * j + 1] = p1[zoff + gn + 1];
        }
    }
#pragma unroll
    for (int i = 0; i < 4; i++) {
        int gmBase = tileM + wm + i * 16 + g;
#pragma unroll
        for (int half = 0; half < 2; half++) {
            int gm = gmBase + half * 8;
            float pmv = 0.f, rsv = 1.f;
            if (mode == 1)      pmv = p2[zoff + gm];
            else if (mode == 2) rsv = p1[zoff + gm];
            float* Crow = C + (long long)gm * ldc;
            float rsum = 0.f;
#pragma unroll
            for (int j = 0; j < 8; j++) {
                int gn = tileN + wn + j * 8 + t4 * 2;
                if (gn >= N) continue;
                float v0 = acc[i][j][half * 2 + 0];
                float v1 = acc[i][j][half * 2 + 1];
                if (mode == 1) {
                    v0 = (gn     <= gm) ? v0 * alpha * __expf(p1v[2 * j    ] - pmv) : 0.f;
                    v1 = (gn + 1 <= gm) ? v1 * alpha * __expf(p1v[2 * j + 1] - pmv) : 0.f;
                    rsum += v0 + v1;
                } else if (mode == 2) {
                    v0 *= rsv; v1 *= rsv;
                } else {
                    v0 *= alpha; v1 *= alpha;
                }
                *reinterpret_cast<float2*>(&Crow[gn]) = make_float2(v0, v1);
            }
            if (mode == 1) {
                rsum += __shfl_xor_sync(0xffffffffu, rsum, 1);
                rsum += __shfl_xor_sync(0xffffffffu, rsum, 2);
                if (t4 == 0) atomicAdd(&p3[zoff + gm], rsum);
            }
        }
    }
}

// ---------------- fused depthwise conv + SiLU + headwise q/k/v -------------
__global__ void convhead_kernel(const float* __restrict__ xmz,
                                const float* __restrict__ w,
                                const float* __restrict__ bias,
                                const float* __restrict__ Wq,
                                const float* __restrict__ Wk,
                                const float* __restrict__ Wv,
                                float* __restrict__ xca,
                                float* __restrict__ q,
                                float* __restrict__ k,
                                float* __restrict__ v)
{
    long long idx = (long long)blockIdx.x * blockDim.x + threadIdx.x;
    long long total = cBS * (long long)cNPH;
    if (idx >= total) return;
    int p = (int)(idx % cNPH);
    long long bs = idx / cNPH;
    int s = (int)(bs % cS);
    int col = p * 4;

    float4 xr[cKS];
#pragma unroll
    for (int tt = 0; tt < cKS; tt++) {
        int sp = s - (cKS - 1) + tt;
        if (sp >= 0)
            xr[tt] = *reinterpret_cast<const float4*>(xmz + (bs - (cKS - 1) + tt) * c2H + col);
        else
            xr[tt] = make_float4(0.f, 0.f, 0.f, 0.f);
    }
    float4 wt[cKS];
#pragma unroll
    for (int tt = 0; tt < cKS; tt++)
        wt[tt] = *reinterpret_cast<const float4*>(w + tt * cH + col);
    float4 bb = *reinterpret_cast<const float4*>(bias + col);

    float4 xc;
    xc.x = bb.x + xr[0].x*wt[0].x + xr[1].x*wt[1].x + xr[2].x*wt[2].x + xr[3].x*wt[3].x;
    xc.y = bb.y + xr[0].y*wt[0].y + xr[1].y*wt[1].y + xr[2].y*wt[2].y + xr[3].y*wt[3].y;
    xc.z = bb.z + xr[0].z*wt[0].z + xr[1].z*wt[1].z + xr[2].z*wt[2].z + xr[3].z*wt[3].z;
    xc.w = bb.w + xr[0].w*wt[0].w + xr[1].w*wt[1].w + xr[2].w*wt[2].w + xr[3].w*wt[3].w;
    xc.x = xc.x / (1.f + __expf(-xc.x));
    xc.y = xc.y / (1.f + __expf(-xc.y));
    xc.z = xc.z / (1.f + __expf(-xc.z));
    xc.w = xc.w / (1.f + __expf(-xc.w));

    long long base = bs * cH + col;
    *reinterpret_cast<float4*>(xca + base) = xc;

    float4 xv = xr[cKS - 1];

    const float4* wq4 = reinterpret_cast<const float4*>(Wq + p * 16);
    const float4* wk4 = reinterpret_cast<const float4*>(Wk + p * 16);
    const float4* wv4 = reinterpret_cast<const float4*>(Wv + p * 16);
    float4 q0 = wq4[0], q1 = wq4[1], q2 = wq4[2], q3 = wq4[3];
    float4 k0 = wk4[0], k1 = wk4[1], k2 = wk4[2], k3 = wk4[3];
    float4 v0 = wv4[0], v1 = wv4[1], v2 = wv4[2], v3 = wv4[3];
    float4 qo, ko, vo;
    qo.x = xc.x*q0.x + xc.y*q1.x + xc.z*q2.x + xc.w*q3.x;
    qo.y = xc.x*q0.y + xc.y*q1.y + xc.z*q2.y + xc.w*q3.y;
    qo.z = xc.x*q0.z + xc.y*q1.z + xc.z*q2.z + xc.w*q3.z;
    qo.w = xc.x*q0.w + xc.y*q1.w + xc.z*q2.w + xc.w*q3.w;
    ko.x = xc.x*k0.x + xc.y*k1.x + xc.z*k2.x + xc.w*k3.x;
    ko.y = xc.x*k0.y + xc.y*k1.y + xc.z*k2.y + xc.w*k3.y;
    ko.z = xc.x*k0.z + xc.y*k1.z + xc.z*k2.z + xc.w*k3.z;
    ko.w = xc.x*k0.w + xc.y*k1.w + xc.z*k2.w + xc.w*k3.w;
    vo.x = xv.x*v0.x + xv.y*v1.x + xv.z*v2.x + xv.w*v3.x;
    vo.y = xv.x*v0.y + xv.y*v1.y + xv.z*v2.y + xv.w*v3.y;
    vo.z = xv.x*v0.z + xv.y*v1.z + xv.z*v2.z + xv.w*v3.z;
    vo.w = xv.x*v0.w + xv.y*v1.w + xv.z*v2.w + xv.w*v3.w;
    *reinterpret_cast<float4*>(q + base) = qo;
    *reinterpret_cast<float4*>(k + base) = ko;
    *reinterpret_cast<float4*>(v + base) = vo;
}

// ---------------- gates: 4 rows/block, warp = (row, K-half) ----------------
__global__ __launch_bounds__(256)
void gates_kernel(const float* __restrict__ q, const float* __restrict__ k,
                  const float* __restrict__ v,
                  const float* __restrict__ Wig, const float* __restrict__ big,
                  const float* __restrict__ Wfg, const float* __restrict__ bfg,
                  float* __restrict__ ipre, float* __restrict__ fpre)
{
    const int warp = threadIdx.x >> 5;
    const int lane = threadIdx.x & 31;
    const int rw   = warp >> 1;
    const int half = warp & 1;
    const long long row = (long long)blockIdx.x * 4 + rw;

    float ai[4] = {0, 0, 0, 0}, af[4] = {0, 0, 0, 0};
    const int rbeg = half * cHALF;
    const int rend = rbeg + cHALF;
    const long long rbase = row * cH;

    for (int r = rbeg + lane; r < rend; r += 32) {
        float4 wi = *reinterpret_cast<const float4*>(Wig + (long long)r * 4);
        float4 wf = *reinterpret_cast<const float4*>(Wfg + (long long)r * 4);
        float val;
        if (r < cH)          val = q[rbase + r];
        else if (r < 2 * cH) val = k[rbase + r - cH];
        else                 val = v[rbase + r - 2 * cH];
        ai[0] += val * wi.x; ai[1] += val * wi.y;
        ai[2] += val * wi.z; ai[3] += val * wi.w;
        af[0] += val * wf.x; af[1] += val * wf.y;
        af[2] += val * wf.z; af[3] += val * wf.w;
    }

#pragma unroll
    for (int o = 16; o > 0; o >>= 1) {
#pragma unroll
        for (int n = 0; n < 4; n++) {
            ai[n] += __shfl_xor_sync(0xffffffffu, ai[n], o);
            af[n] += __shfl_xor_sync(0xffffffffu, af[n], o);
        }
    }

    __shared__ float part[4][8];
    if (half == 1 && lane == 0) {
#pragma unroll
        for (int n = 0; n < 4; n++) { part[rw][n] = ai[n]; part[rw][4 + n] = af[n]; }
    }
    __syncthreads();
    if (half == 0 && lane == 0) {
        int b = (int)(row / cS), s = (int)(row % cS);
#pragma unroll
        for (int n = 0; n < 4; n++) {
            ipre[(long long)(b * cNH + n) * cS + s] = ai[n] + part[rw][n]     + big[n];
            fpre[(long long)(b * cNH + n) * cS + s] = af[n] + part[rw][4 + n] + bfg[n];
        }
    }
}

// ---------------- scan ----------------
__global__ __launch_bounds__(256)
void scan_kernel(const float* __restrict__ ipre, const float* __restrict__ fpre,
                 float* __restrict__ cs, float* __restrict__ aArr,
                 float* __restrict__ pm, float* __restrict__ nsum)
{
    int bh = blockIdx.x;
    int t  = threadIdx.x;
    const float* fp = fpre + (long long)bh * cS;
    const float* ip = ipre + (long long)bh * cS;

    float loc[8];
    float sum = 0.f;
#pragma unroll
    for (int u = 0; u < 8; u++) {
        int j = t * 8 + u;
        float f = fp[j];
        float lf = fminf(f, 0.f) - log1pf(expf(-fabsf(f)));
        sum += lf;
        loc[u] = sum;
    }
    __shared__ float part[256];
    part[t] = sum;
    __syncthreads();
    for (int off = 1; off < 256; off <<= 1) {
        float vv = (t >= off) ? part[t - off] : 0.f;
        __syncthreads();
        part[t] += vv;
        __syncthreads();
    }
    float excl = part[t] - sum;

    float lmax[8];
    float amax = -1e30f;
#pragma unroll
    for (int u = 0; u < 8; u++) {
        int j = t * 8 + u;
        float csj = excl + loc[u];
        cs[(long long)bh * cS + j] = csj;
        float aj = ip[j] - csj;
        aArr[(long long)bh * cS + j] = aj;
        nsum[(long long)bh * cS + j] = 0.f;
        amax = fmaxf(amax, aj);
        lmax[u] = amax;
    }
    __syncthreads();
    part[t] = amax;
    __syncthreads();
    for (int off = 1; off < 256; off <<= 1) {
        float vv = (t >= off) ? part[t - off] : -1e30f;
        __syncthreads();
        part[t] = fmaxf(part[t], vv);
        __syncthreads();
    }
    float exmax = (t > 0) ? part[t - 1] : -1e30f;
#pragma unroll
    for (int u = 0; u < 8; u++) {
        int j = t * 8 + u;
        pm[(long long)bh * cS + j] = fmaxf(exmax, lmax[u]);
    }
}

// ---------------- finalize n -> rs ----------------
__global__ void nfin_kernel(const float* __restrict__ nsum,
                            const float* __restrict__ cs, const float* __restrict__ pm,
                            float* __restrict__ rs)
{
    int idx = blockIdx.x * blockDim.x + threadIdx.x;
    if (idx >= cBHS) return;
    float m = cs[idx] + pm[idx];
    float n = fmaxf(fabsf(nsum[idx]), __expf(-m));
    rs[idx] = 1.f / (n + 1e-6f);
}

// ---------------- multi-head LN + skip + z-gate ----------------
__global__ __launch_bounds__(256)
void ln_kernel(const float* __restrict__ hbuf, const float* __restrict__ xca,
               const float* __restrict__ xmz, const float* __restrict__ norm_w,
               const float* __restrict__ skip, float* __restrict__ hs)
{
    int s  = blockIdx.x;
    int bh = blockIdx.y;
    int t  = threadIdx.x;
    int b = bh / cNH, n = bh % cNH;
    const float* hrow = hbuf + ((long long)bh * cS + s) * cDH;

    float sum = 0.f, ss = 0.f;
    for (int d = t; d < cDH; d += 256) {
        float v = hrow[d];
        sum += v; ss += v * v;
    }
    __shared__ float r1[256], r2[256];
    r1[t] = sum; r2[t] = ss;
    __syncthreads();
    for (int o = 128; o > 0; o >>= 1) {
        if (t < o) { r1[t] += r1[t + o]; r2[t] += r2[t + o]; }
        __syncthreads();
    }
    float mean = r1[0] / cDH;
    float var  = r2[0] / cDH - mean * mean;
    float inv  = rsqrtf(var + 1e-5f);

    long long bsRow = (long long)b * cS + s;
    long long xbase = bsRow * cH;
    long long zbase = bsRow * c2H + cH;
    for (int d = t; d < cDH; d += 256) {
        int col = n * cDH + d;
        float hn = (hrow[d] - mean) * inv * norm_w[col];
        float hk = hn + skip[col] * xca[xbase + col];
        float zv = xmz[zbase + col];
        float sz = zv / (1.f + __expf(-zv));
        hs[xbase + col] = hk * sz;
    }
}

// ---------------- launch ----------------
extern "C" void kernel_launch(void* const* d_in, const int* in_sizes, int n_in,
                              void* d_out, int out_size)
{
    const float* x      = (const float*)d_in[0];
    const float* W_in   = (const float*)d_in[1];
    const float* conv_w = (const float*)d_in[2];
    const float* conv_b = (const float*)d_in[3];
    const float* Wq     = (const float*)d_in[4];
    const float* Wk     = (const float*)d_in[5];
    const float* Wv     = (const float*)d_in[6];
    const float* W_ig   = (const float*)d_in[7];
    const float* b_ig   = (const float*)d_in[8];
    const float* W_fg   = (const float*)d_in[9];
    const float* b_fg   = (const float*)d_in[10];
    const float* norm_w = (const float*)d_in[11];
    const float* skip   = (const float*)d_in[12];
    const float* W_out  = (const float*)d_in[13];
    float* out = (float*)d_out;

    float *p_xmz, *p_xca, *p_q, *p_k, *p_v, *p_h, *p_hs, *p_sc;
    float *p_ipre, *p_fpre, *p_cs, *p_a, *p_pm, *p_rs, *p_ns;
    cudaGetSymbolAddress((void**)&p_xmz, g_xmz);
    cudaGetSymbolAddress((void**)&p_xca, g_xca);
    cudaGetSymbolAddress((void**)&p_q,   g_q);
    cudaGetSymbolAddress((void**)&p_k,   g_k);
    cudaGetSymbolAddress((void**)&p_v,   g_v);
    cudaGetSymbolAddress((void**)&p_h,   g_h);
    cudaGetSymbolAddress((void**)&p_hs,  g_hs);
    cudaGetSymbolAddress((void**)&p_sc,  g_scores);
    cudaGetSymbolAddress((void**)&p_ipre, g_ipre);
    cudaGetSymbolAddress((void**)&p_fpre, g_fpre);
    cudaGetSymbolAddress((void**)&p_cs,  g_cs);
    cudaGetSymbolAddress((void**)&p_a,   g_a);
    cudaGetSymbolAddress((void**)&p_pm,  g_pm);
    cudaGetSymbolAddress((void**)&p_rs,  g_rs);
    cudaGetSymbolAddress((void**)&p_ns,  g_nsum);

    cudaFuncSetAttribute(tgemm_kernel, cudaFuncAttributeMaxDynamicSharedMemorySize, SMEMSZ);

    const int M0 = (int)cBS;  // 4096

    // 1) x @ W_in -> xmz (merged, N = 2H)
    {
        dim3 grid(c2H / BN, M0 / BM, 1);
        tgemm_kernel<<<grid, 256, SMEMSZ>>>(M0, c2H, cE,
            x, cE, 0, 0,
            W_in, c2H, 0, 0,
            p_xmz, c2H, 0, 0,
            1, 0, 0, 1.0f, nullptr, nullptr, nullptr, 0);
    }

    // 2+3) fused conv + SiLU + headwise q/k/v
    {
        long long total = cBS * (long long)cNPH;
        int blocks = (int)((total + 255) / 256);
        convhead_kernel<<<blocks, 256>>>(p_xmz, conv_w, conv_b, Wq, Wk, Wv,
                                         p_xca, p_q, p_k, p_v);
    }

    // 4) gates
    gates_kernel<<<M0 / 4, 256>>>(p_q, p_k, p_v, W_ig, b_ig, W_fg, b_fg, p_ipre, p_fpre);

    // 5) scan (also zeroes nsum)
    scan_kernel<<<cB * cNH, 256>>>(p_ipre, p_fpre, p_cs, p_a, p_pm, p_ns);

    // 6) scores (mode 1, fused row sums, causal tile skip)
    {
        dim3 grid(cS / BN, cS / BM, cB * cNH);
        float alpha = 1.0f / sqrtf((float)cDH);
        tgemm_kernel<<<grid, 256, SMEMSZ>>>(cS, cS, cDH,
            p_q, cH, (long long)cS * cH, (long long)cDH,
            p_k, cH, (long long)cS * cH, (long long)cDH,
            p_sc, cS, (long long)cNH * cS * cS, (long long)cS * cS,
            cNH, 1, 1, alpha, p_a, p_pm, p_ns, cS);
    }

    // 7) finalize rs
    nfin_kernel<<<(cBHS + 255) / 256, 256>>>(p_ns, p_cs, p_pm, p_rs);

    // 8) h = diag(rs) * scores @ v (mode 2, causal K-limit)
    {
        dim3 grid((cDH + BN - 1) / BN, cS / BM, cB * cNH);
        tgemm_kernel<<<grid, 256, SMEMSZ>>>(cS, cDH, cS,
            p_sc, cS, (long long)cNH * cS * cS, (long long)cS * cS,
            p_v, cH, (long long)cS * cH, (long long)cDH,
            p_h, cDH, (long long)cNH * cS * cDH, (long long)cS * cDH,
            cNH, 0, 2, 1.0f, p_rs, nullptr, nullptr, cS);
    }

    // 9) LN + skip + z gate
    {
        dim3 grid(cS, cB * cNH);
        ln_kernel<<<grid, 256>>>(p_h, p_xca, p_xmz, norm_w, skip, p_hs);
    }

    // 10) out = hs @ W_out
    {
        dim3 grid(cE / BN, M0 / BM, 1);
        tgemm_kernel<<<grid, 256, SMEMSZ>>>(M0, cE, cH,
            p_hs, cH, 0, 0,
            W_out, cE, 0, 0,
            out, cE, 0, 0,
            1, 0, 0, 1.0f, nullptr, nullptr, nullptr, 0);
    }
}

// round 12
// speedup vs baseline: 1.4773x; 1.4773x over previous
#include <cuda_runtime.h>
#include <cuda_fp16.h>
#include <math.h>
#include <stdint.h>

// ---------------- problem dims ----------------
constexpr int cB   = 2;
constexpr int cS   = 2048;
constexpr int cE   = 2048;
constexpr int cH   = 2688;
constexpr int c2H  = 2 * cH;
constexpr int cNH  = 4;
constexpr int cDH  = 672;
constexpr int cKS  = 4;
constexpr int cNPH = 672;
constexpr long long cBS  = (long long)cB * cS;        // 4096
constexpr long long cBSH = cBS * cH;
constexpr long long cSCORES = (long long)cB * cNH * cS * cS;
constexpr int cBHS = cB * cNH * cS;
constexpr int c3H  = 3 * cH;
constexpr int cHALF = c3H / 2;

// ---------------- device scratch ----------------
__device__ float g_xmz[cBS * (long long)c2H];
__device__ float g_xca[cBSH];
__device__ float g_q  [cBSH];
__device__ float g_k  [cBSH];
__device__ float g_v  [cBSH];
__device__ float g_h  [cBSH];
__device__ float g_hs [cBSH];
__device__ float g_scores[cSCORES];
__device__ float g_ipre[cBHS];
__device__ float g_fpre[cBHS];
__device__ float g_cs  [cBHS];
__device__ float g_a   [cBHS];
__device__ float g_pm  [cBHS];
__device__ float g_rs  [cBHS];
__device__ float g_nsum[cBHS];

// ---------------- helpers ----------------
__device__ __forceinline__ uint32_t packh2(float lo, float hi) {
    __half2 h = __floats2half2_rn(lo, hi);
    return *reinterpret_cast<uint32_t*>(&h);
}
__device__ __forceinline__ void cp16(uint32_t saddr, const void* gptr, int bytes) {
    asm volatile("cp.async.cg.shared.global [%0], [%1], 16, %2;\n"
                 :: "r"(saddr), "l"(gptr), "r"(bytes));
}
__device__ __forceinline__ void cp_commit() { asm volatile("cp.async.commit_group;\n" ::: "memory"); }
__device__ __forceinline__ void cp_wait0()  { asm volatile("cp.async.wait_group 0;\n" ::: "memory"); }

#define MMA_F16(d, a, b)                                                       \
    asm volatile(                                                              \
        "mma.sync.aligned.m16n8k16.row.col.f32.f16.f16.f32 "                   \
        "{%0,%1,%2,%3},{%4,%5,%6,%7},{%8,%9},{%0,%1,%2,%3};\n"                 \
        : "+f"(d[0]), "+f"(d[1]), "+f"(d[2]), "+f"(d[3])                       \
        : "r"(a[0]), "r"(a[1]), "r"(a[2]), "r"(a[3]), "r"(b[0]), "r"(b[1]))

// ---------------- fp16 tensor-core GEMM (cp.async double buffered) ---------
// fp32 tiles in smem, converted to half2 at fragment load (same mantissa as
// tf32 -> same accuracy class). One m16n8k16 per warp-subtile per BK=16 iter.
// mode 0: C = alpha * acc
// mode 1: scores epilogue + fused causal row sums into p3 (atomics)
// mode 2: row scale by p1[m]; K limited to tileM+128 (A lower-tri)
#define BM 128
#define BN 128
#define BK 16
#define ASTR 24    // BK + 8
#define BSTR 132   // BN + 4

__global__ __launch_bounds__(256)
void tgemm_kernel(int M, int N, int K,
                  const float* __restrict__ A, int lda, long long sAb, long long sAn,
                  const float* __restrict__ B, int ldb, long long sBb, long long sBn,
                  float* __restrict__ C, int ldc, long long sCb, long long sCn,
                  int nhd, int transB, int mode, float alpha,
                  const float* __restrict__ p1, const float* __restrict__ p2,
                  float* __restrict__ p3, int pstr)
{
    const int z  = blockIdx.z;
    const int zb = z / nhd, zn = z % nhd;
    A += zb * sAb + zn * sAn;
    B += zb * sBb + zn * sBn;
    C += zb * sCb + zn * sCn;

    const int tileM = blockIdx.y * BM;
    const int tileN = blockIdx.x * BN;
    if (mode == 1 && tileN > tileM + BM - 1) return;   // fully masked tile

    const int t    = threadIdx.x;
    const int lane = t & 31;
    const int warp = t >> 5;
    const int g    = lane >> 2;     // 0..7
    const int t4   = lane & 3;      // 0..3
    const int wm   = (warp & 1) * 64;
    const int wn   = (warp >> 1) * 32;

    __shared__ float As[2][BM * ASTR];             // 2 x 12 KB
    __shared__ float Bs[2][BM * ASTR];             // NT: 128*24; NN: 16*132 fits

    float acc[4][4][4];
#pragma unroll
    for (int i = 0; i < 4; i++)
#pragma unroll
        for (int j = 0; j < 4; j++)
#pragma unroll
            for (int r = 0; r < 4; r++) acc[i][j][r] = 0.f;

    int Kend = K;
    if (mode == 2) { int lim = tileM + BM; Kend = lim < K ? lim : K; }
    const int nIter = Kend / BK;

    uint32_t sA[2], sB[2];
    sA[0] = (uint32_t)__cvta_generic_to_shared(&As[0][0]);
    sA[1] = (uint32_t)__cvta_generic_to_shared(&As[1][0]);
    sB[0] = (uint32_t)__cvta_generic_to_shared(&Bs[0][0]);
    sB[1] = (uint32_t)__cvta_generic_to_shared(&Bs[1][0]);

    auto loadTiles = [&](int stg, int k0) {
        // A tile: 128 rows x 16 cols = 256 8-float chunks, one per thread
        {
            int row = t >> 1;
            int kc  = (t & 1) * 8;
            const float* gp = &A[(long long)(tileM + row) * lda + k0 + kc];
            cp16(sA[stg] + (row * ASTR + kc) * 4, gp, 16);
            cp16(sA[stg] + (row * ASTR + kc + 4) * 4, gp + 4, 16);
        }
        if (!transB) {
#pragma unroll
            for (int hh = 0; hh < 2; hh++) {
                int c  = t + hh * 256;
                int kr = c >> 5;
                int n4 = (c & 31) * 4;
                int gn = tileN + n4;
                int ok = (gn < N);
                const float* gp = &B[(long long)(k0 + kr) * ldb + (ok ? gn : 0)];
                cp16(sB[stg] + (kr * BSTR + n4) * 4, gp, ok ? 16 : 0);
            }
        } else {
            int row = t >> 1;
            int kc  = (t & 1) * 8;
            const float* gp = &B[(long long)(tileN + row) * ldb + k0 + kc];
            cp16(sB[stg] + (row * ASTR + kc) * 4, gp, 16);
            cp16(sB[stg] + (row * ASTR + kc + 4) * 4, gp + 4, 16);
        }
        cp_commit();
    };

    loadTiles(0, 0);
    cp_wait0();
    __syncthreads();

    for (int it = 0; it < nIter; it++) {
        const int s  = it & 1;
        const int kn = (it + 1) * BK;
        const bool more = (kn < Kend);
        if (more) loadTiles(s ^ 1, kn);

        const float* Asb = As[s];
        const float* Bsb = Bs[s];

        uint32_t af[4][4], bf[4][2];
#pragma unroll
        for (int i = 0; i < 4; i++) {
            int m0 = wm + i * 16 + g;
            const float* r0 = &Asb[(m0    ) * ASTR];
            const float* r1 = &Asb[(m0 + 8) * ASTR];
            float2 v0 = *reinterpret_cast<const float2*>(r0 + 2 * t4);
            float2 v1 = *reinterpret_cast<const float2*>(r1 + 2 * t4);
            float2 v2 = *reinterpret_cast<const float2*>(r0 + 2 * t4 + 8);
            float2 v3 = *reinterpret_cast<const float2*>(r1 + 2 * t4 + 8);
            af[i][0] = packh2(v0.x, v0.y);
            af[i][1] = packh2(v1.x, v1.y);
            af[i][2] = packh2(v2.x, v2.y);
            af[i][3] = packh2(v3.x, v3.y);
        }
#pragma unroll
        for (int j = 0; j < 4; j++) {
            int n0 = wn + j * 8 + g;
            if (transB) {
                const float* rb = &Bsb[n0 * ASTR];
                float2 w0 = *reinterpret_cast<const float2*>(rb + 2 * t4);
                float2 w1 = *reinterpret_cast<const float2*>(rb + 2 * t4 + 8);
                bf[j][0] = packh2(w0.x, w0.y);
                bf[j][1] = packh2(w1.x, w1.y);
            } else {
                float b0 = Bsb[(2 * t4    ) * BSTR + n0];
                float b1 = Bsb[(2 * t4 + 1) * BSTR + n0];
                float b2 = Bsb[(2 * t4 + 8) * BSTR + n0];
                float b3 = Bsb[(2 * t4 + 9) * BSTR + n0];
                bf[j][0] = packh2(b0, b1);
                bf[j][1] = packh2(b2, b3);
            }
        }
#pragma unroll
        for (int i = 0; i < 4; i++)
#pragma unroll
            for (int j = 0; j < 4; j++)
                MMA_F16(acc[i][j], af[i], bf[j]);

        if (more) cp_wait0();
        __syncthreads();
    }

    // ---- epilogue ----
    const long long zoff = (long long)z * pstr;
    float p1v[8];
    if (mode == 1) {
#pragma unroll
        for (int j = 0; j < 4; j++) {
            int gn = tileN + wn + j * 8 + t4 * 2;
            p1v[2 * j]     = p1[zoff + gn];
            p1v[2 * j + 1] = p1[zoff + gn + 1];
        }
    }
#pragma unroll
    for (int i = 0; i < 4; i++) {
        int gmBase = tileM + wm + i * 16 + g;
#pragma unroll
        for (int half = 0; half < 2; half++) {
            int gm = gmBase + half * 8;
            float pmv = 0.f, rsv = 1.f;
            if (mode == 1)      pmv = p2[zoff + gm];
            else if (mode == 2) rsv = p1[zoff + gm];
            float* Crow = C + (long long)gm * ldc;
            float rsum = 0.f;
#pragma unroll
            for (int j = 0; j < 4; j++) {
                int gn = tileN + wn + j * 8 + t4 * 2;
                if (gn >= N) continue;
                float v0 = acc[i][j][half * 2 + 0];
                float v1 = acc[i][j][half * 2 + 1];
                if (mode == 1) {
                    v0 = (gn     <= gm) ? v0 * alpha * __expf(p1v[2 * j    ] - pmv) : 0.f;
                    v1 = (gn + 1 <= gm) ? v1 * alpha * __expf(p1v[2 * j + 1] - pmv) : 0.f;
                    rsum += v0 + v1;
                } else if (mode == 2) {
                    v0 *= rsv; v1 *= rsv;
                } else {
                    v0 *= alpha; v1 *= alpha;
                }
                *reinterpret_cast<float2*>(&Crow[gn]) = make_float2(v0, v1);
            }
            if (mode == 1) {
                rsum += __shfl_xor_sync(0xffffffffu, rsum, 1);
                rsum += __shfl_xor_sync(0xffffffffu, rsum, 2);
                if (t4 == 0) atomicAdd(&p3[zoff + gm], rsum);
            }
        }
    }
}

// ---------------- fused depthwise conv + SiLU + headwise q/k/v -------------
__global__ void convhead_kernel(const float* __restrict__ xmz,
                                const float* __restrict__ w,
                                const float* __restrict__ bias,
                                const float* __restrict__ Wq,
                                const float* __restrict__ Wk,
                                const float* __restrict__ Wv,
                                float* __restrict__ xca,
                                float* __restrict__ q,
                                float* __restrict__ k,
                                float* __restrict__ v)
{
    long long idx = (long long)blockIdx.x * blockDim.x + threadIdx.x;
    long long total = cBS * (long long)cNPH;
    if (idx >= total) return;
    int p = (int)(idx % cNPH);
    long long bs = idx / cNPH;
    int s = (int)(bs % cS);
    int col = p * 4;

    float4 xr[cKS];
#pragma unroll
    for (int tt = 0; tt < cKS; tt++) {
        int sp = s - (cKS - 1) + tt;
        if (sp >= 0)
            xr[tt] = *reinterpret_cast<const float4*>(xmz + (bs - (cKS - 1) + tt) * c2H + col);
        else
            xr[tt] = make_float4(0.f, 0.f, 0.f, 0.f);
    }
    float4 wt[cKS];
#pragma unroll
    for (int tt = 0; tt < cKS; tt++)
        wt[tt] = *reinterpret_cast<const float4*>(w + tt * cH + col);
    float4 bb = *reinterpret_cast<const float4*>(bias + col);

    float4 xc;
    xc.x = bb.x + xr[0].x*wt[0].x + xr[1].x*wt[1].x + xr[2].x*wt[2].x + xr[3].x*wt[3].x;
    xc.y = bb.y + xr[0].y*wt[0].y + xr[1].y*wt[1].y + xr[2].y*wt[2].y + xr[3].y*wt[3].y;
    xc.z = bb.z + xr[0].z*wt[0].z + xr[1].z*wt[1].z + xr[2].z*wt[2].z + xr[3].z*wt[3].z;
    xc.w = bb.w + xr[0].w*wt[0].w + xr[1].w*wt[1].w + xr[2].w*wt[2].w + xr[3].w*wt[3].w;
    xc.x = xc.x / (1.f + __expf(-xc.x));
    xc.y = xc.y / (1.f + __expf(-xc.y));
    xc.z = xc.z / (1.f + __expf(-xc.z));
    xc.w = xc.w / (1.f + __expf(-xc.w));

    long long base = bs * cH + col;
    *reinterpret_cast<float4*>(xca + base) = xc;

    float4 xv = xr[cKS - 1];

    const float4* wq4 = reinterpret_cast<const float4*>(Wq + p * 16);
    const float4* wk4 = reinterpret_cast<const float4*>(Wk + p * 16);
    const float4* wv4 = reinterpret_cast<const float4*>(Wv + p * 16);
    float4 q0 = wq4[0], q1 = wq4[1], q2 = wq4[2], q3 = wq4[3];
    float4 k0 = wk4[0], k1 = wk4[1], k2 = wk4[2], k3 = wk4[3];
    float4 v0 = wv4[0], v1 = wv4[1], v2 = wv4[2], v3 = wv4[3];
    float4 qo, ko, vo;
    qo.x = xc.x*q0.x + xc.y*q1.x + xc.z*q2.x + xc.w*q3.x;
    qo.y = xc.x*q0.y + xc.y*q1.y + xc.z*q2.y + xc.w*q3.y;
    qo.z = xc.x*q0.z + xc.y*q1.z + xc.z*q2.z + xc.w*q3.z;
    qo.w = xc.x*q0.w + xc.y*q1.w + xc.z*q2.w + xc.w*q3.w;
    ko.x = xc.x*k0.x + xc.y*k1.x + xc.z*k2.x + xc.w*k3.x;
    ko.y = xc.x*k0.y + xc.y*k1.y + xc.z*k2.y + xc.w*k3.y;
    ko.z = xc.x*k0.z + xc.y*k1.z + xc.z*k2.z + xc.w*k3.z;
    ko.w = xc.x*k0.w + xc.y*k1.w + xc.z*k2.w + xc.w*k3.w;
    vo.x = xv.x*v0.x + xv.y*v1.x + xv.z*v2.x + xv.w*v3.x;
    vo.y = xv.x*v0.y + xv.y*v1.y + xv.z*v2.y + xv.w*v3.y;
    vo.z = xv.x*v0.z + xv.y*v1.z + xv.z*v2.z + xv.w*v3.z;
    vo.w = xv.x*v0.w + xv.y*v1.w + xv.z*v2.w + xv.w*v3.w;
    *reinterpret_cast<float4*>(q + base) = qo;
    *reinterpret_cast<float4*>(k + base) = ko;
    *reinterpret_cast<float4*>(v + base) = vo;
}

// ---------------- gates: 4 rows/block, warp = (row, K-half) ----------------
__global__ __launch_bounds__(256)
void gates_kernel(const float* __restrict__ q, const float* __restrict__ k,
                  const float* __restrict__ v,
                  const float* __restrict__ Wig, const float* __restrict__ big,
                  const float* __restrict__ Wfg, const float* __restrict__ bfg,
                  float* __restrict__ ipre, float* __restrict__ fpre)
{
    const int warp = threadIdx.x >> 5;
    const int lane = threadIdx.x & 31;
    const int rw   = warp >> 1;
    const int half = warp & 1;
    const long long row = (long long)blockIdx.x * 4 + rw;

    float ai[4] = {0, 0, 0, 0}, af[4] = {0, 0, 0, 0};
    const int rbeg = half * cHALF;
    const int rend = rbeg + cHALF;
    const long long rbase = row * cH;

    for (int r = rbeg + lane; r < rend; r += 32) {
        float4 wi = *reinterpret_cast<const float4*>(Wig + (long long)r * 4);
        float4 wf = *reinterpret_cast<const float4*>(Wfg + (long long)r * 4);
        float val;
        if (r < cH)          val = q[rbase + r];
        else if (r < 2 * cH) val = k[rbase + r - cH];
        else                 val = v[rbase + r - 2 * cH];
        ai[0] += val * wi.x; ai[1] += val * wi.y;
        ai[2] += val * wi.z; ai[3] += val * wi.w;
        af[0] += val * wf.x; af[1] += val * wf.y;
        af[2] += val * wf.z; af[3] += val * wf.w;
    }

#pragma unroll
    for (int o = 16; o > 0; o >>= 1) {
#pragma unroll
        for (int n = 0; n < 4; n++) {
            ai[n] += __shfl_xor_sync(0xffffffffu, ai[n], o);
            af[n] += __shfl_xor_sync(0xffffffffu, af[n], o);
        }
    }

    __shared__ float part[4][8];
    if (half == 1 && lane == 0) {
#pragma unroll
        for (int n = 0; n < 4; n++) { part[rw][n] = ai[n]; part[rw][4 + n] = af[n]; }
    }
    __syncthreads();
    if (half == 0 && lane == 0) {
        int b = (int)(row / cS), s = (int)(row % cS);
#pragma unroll
        for (int n = 0; n < 4; n++) {
            ipre[(long long)(b * cNH + n) * cS + s] = ai[n] + part[rw][n]     + big[n];
            fpre[(long long)(b * cNH + n) * cS + s] = af[n] + part[rw][4 + n] + bfg[n];
        }
    }
}

// ---------------- scan ----------------
__global__ __launch_bounds__(256)
void scan_kernel(const float* __restrict__ ipre, const float* __restrict__ fpre,
                 float* __restrict__ cs, float* __restrict__ aArr,
                 float* __restrict__ pm, float* __restrict__ nsum)
{
    int bh = blockIdx.x;
    int t  = threadIdx.x;
    const float* fp = fpre + (long long)bh * cS;
    const float* ip = ipre + (long long)bh * cS;

    float loc[8];
    float sum = 0.f;
#pragma unroll
    for (int u = 0; u < 8; u++) {
        int j = t * 8 + u;
        float f = fp[j];
        float lf = fminf(f, 0.f) - log1pf(expf(-fabsf(f)));
        sum += lf;
        loc[u] = sum;
    }
    __shared__ float part[256];
    part[t] = sum;
    __syncthreads();
    for (int off = 1; off < 256; off <<= 1) {
        float vv = (t >= off) ? part[t - off] : 0.f;
        __syncthreads();
        part[t] += vv;
        __syncthreads();
    }
    float excl = part[t] - sum;

    float lmax[8];
    float amax = -1e30f;
#pragma unroll
    for (int u = 0; u < 8; u++) {
        int j = t * 8 + u;
        float csj = excl + loc[u];
        cs[(long long)bh * cS + j] = csj;
        float aj = ip[j] - csj;
        aArr[(long long)bh * cS + j] = aj;
        nsum[(long long)bh * cS + j] = 0.f;
        amax = fmaxf(amax, aj);
        lmax[u] = amax;
    }
    __syncthreads();
    part[t] = amax;
    __syncthreads();
    for (int off = 1; off < 256; off <<= 1) {
        float vv = (t >= off) ? part[t - off] : -1e30f;
        __syncthreads();
        part[t] = fmaxf(part[t], vv);
        __syncthreads();
    }
    float exmax = (t > 0) ? part[t - 1] : -1e30f;
#pragma unroll
    for (int u = 0; u < 8; u++) {
        int j = t * 8 + u;
        pm[(long long)bh * cS + j] = fmaxf(exmax, lmax[u]);
    }
}

// ---------------- finalize n -> rs ----------------
__global__ void nfin_kernel(const float* __restrict__ nsum,
                            const float* __restrict__ cs, const float* __restrict__ pm,
                            float* __restrict__ rs)
{
    int idx = blockIdx.x * blockDim.x + threadIdx.x;
    if (idx >= cBHS) return;
    float m = cs[idx] + pm[idx];
    float n = fmaxf(fabsf(nsum[idx]), __expf(-m));
    rs[idx] = 1.f / (n + 1e-6f);
}

// ---------------- multi-head LN + skip + z-gate ----------------
__global__ __launch_bounds__(256)
void ln_kernel(const float* __restrict__ hbuf, const float* __restrict__ xca,
               const float* __restrict__ xmz, const float* __restrict__ norm_w,
               const float* __restrict__ skip, float* __restrict__ hs)
{
    int s  = blockIdx.x;
    int bh = blockIdx.y;
    int t  = threadIdx.x;
    int b = bh / cNH, n = bh % cNH;
    const float* hrow = hbuf + ((long long)bh * cS + s) * cDH;

    float sum = 0.f, ss = 0.f;
    for (int d = t; d < cDH; d += 256) {
        float v = hrow[d];
        sum += v; ss += v * v;
    }
    __shared__ float r1[256], r2[256];
    r1[t] = sum; r2[t] = ss;
    __syncthreads();
    for (int o = 128; o > 0; o >>= 1) {
        if (t < o) { r1[t] += r1[t + o]; r2[t] += r2[t + o]; }
        __syncthreads();
    }
    float mean = r1[0] / cDH;
    float var  = r2[0] / cDH - mean * mean;
    float inv  = rsqrtf(var + 1e-5f);

    long long bsRow = (long long)b * cS + s;
    long long xbase = bsRow * cH;
    long long zbase = bsRow * c2H + cH;
    for (int d = t; d < cDH; d += 256) {
        int col = n * cDH + d;
        float hn = (hrow[d] - mean) * inv * norm_w[col];
        float hk = hn + skip[col] * xca[xbase + col];
        float zv = xmz[zbase + col];
        float sz = zv / (1.f + __expf(-zv));
        hs[xbase + col] = hk * sz;
    }
}

// ---------------- launch ----------------
extern "C" void kernel_launch(void* const* d_in, const int* in_sizes, int n_in,
                              void* d_out, int out_size)
{
    const float* x      = (const float*)d_in[0];
    const float* W_in   = (const float*)d_in[1];
    const float* conv_w = (const float*)d_in[2];
    const float* conv_b = (const float*)d_in[3];
    const float* Wq     = (const float*)d_in[4];
    const float* Wk     = (const float*)d_in[5];
    const float* Wv     = (const float*)d_in[6];
    const float* W_ig   = (const float*)d_in[7];
    const float* b_ig   = (const float*)d_in[8];
    const float* W_fg   = (const float*)d_in[9];
    const float* b_fg   = (const float*)d_in[10];
    const float* norm_w = (const float*)d_in[11];
    const float* skip   = (const float*)d_in[12];
    const float* W_out  = (const float*)d_in[13];
    float* out = (float*)d_out;

    float *p_xmz, *p_xca, *p_q, *p_k, *p_v, *p_h, *p_hs, *p_sc;
    float *p_ipre, *p_fpre, *p_cs, *p_a, *p_pm, *p_rs, *p_ns;
    cudaGetSymbolAddress((void**)&p_xmz, g_xmz);
    cudaGetSymbolAddress((void**)&p_xca, g_xca);
    cudaGetSymbolAddress((void**)&p_q,   g_q);
    cudaGetSymbolAddress((void**)&p_k,   g_k);
    cudaGetSymbolAddress((void**)&p_v,   g_v);
    cudaGetSymbolAddress((void**)&p_h,   g_h);
    cudaGetSymbolAddress((void**)&p_hs,  g_hs);
    cudaGetSymbolAddress((void**)&p_sc,  g_scores);
    cudaGetSymbolAddress((void**)&p_ipre, g_ipre);
    cudaGetSymbolAddress((void**)&p_fpre, g_fpre);
    cudaGetSymbolAddress((void**)&p_cs,  g_cs);
    cudaGetSymbolAddress((void**)&p_a,   g_a);
    cudaGetSymbolAddress((void**)&p_pm,  g_pm);
    cudaGetSymbolAddress((void**)&p_rs,  g_rs);
    cudaGetSymbolAddress((void**)&p_ns,  g_nsum);

    const int M0 = (int)cBS;  // 4096

    // 1) x @ W_in -> xmz (merged, N = 2H)
    {
        dim3 grid(c2H / BN, M0 / BM, 1);
        tgemm_kernel<<<grid, 256>>>(M0, c2H, cE,
            x, cE, 0, 0,
            W_in, c2H, 0, 0,
            p_xmz, c2H, 0, 0,
            1, 0, 0, 1.0f, nullptr, nullptr, nullptr, 0);
    }

    // 2+3) fused conv + SiLU + headwise q/k/v
    {
        long long total = cBS * (long long)cNPH;
        int blocks = (int)((total + 255) / 256);
        convhead_kernel<<<blocks, 256>>>(p_xmz, conv_w, conv_b, Wq, Wk, Wv,
                                         p_xca, p_q, p_k, p_v);
    }

    // 4) gates
    gates_kernel<<<M0 / 4, 256>>>(p_q, p_k, p_v, W_ig, b_ig, W_fg, b_fg, p_ipre, p_fpre);

    // 5) scan (also zeroes nsum)
    scan_kernel<<<cB * cNH, 256>>>(p_ipre, p_fpre, p_cs, p_a, p_pm, p_ns);

    // 6) scores (mode 1, fused row sums, causal tile skip)
    {
        dim3 grid(cS / BN, cS / BM, cB * cNH);
        float alpha = 1.0f / sqrtf((float)cDH);
        tgemm_kernel<<<grid, 256>>>(cS, cS, cDH,
            p_q, cH, (long long)cS * cH, (long long)cDH,
            p_k, cH, (long long)cS * cH, (long long)cDH,
            p_sc, cS, (long long)cNH * cS * cS, (long long)cS * cS,
            cNH, 1, 1, alpha, p_a, p_pm, p_ns, cS);
    }

    // 7) finalize rs
    nfin_kernel<<<(cBHS + 255) / 256, 256>>>(p_ns, p_cs, p_pm, p_rs);

    // 8) h = diag(rs) * scores @ v (mode 2, causal K-limit)
    {
        dim3 grid((cDH + BN - 1) / BN, cS / BM, cB * cNH);
        tgemm_kernel<<<grid, 256>>>(cS, cDH, cS,
            p_sc, cS, (long long)cNH * cS * cS, (long long)cS * cS,
            p_v, cH, (long long)cS * cH, (long long)cDH,
            p_h, cDH, (long long)cNH * cS * cDH, (long long)cS * cDH,
            cNH, 0, 2, 1.0f, p_rs, nullptr, nullptr, cS);
    }

    // 9) LN + skip + z gate
    {
        dim3 grid(cS, cB * cNH);
        ln_kernel<<<grid, 256>>>(p_h, p_xca, p_xmz, norm_w, skip, p_hs);
    }

    // 10) out = hs @ W_out
    {
        dim3 grid(cE / BN, M0 / BM, 1);
        tgemm_kernel<<<grid, 256>>>(M0, cE, cH,
            p_hs, cH, 0, 0,
            W_out, cE, 0, 0,
            out, cE, 0, 0,
            1, 0, 0, 1.0f, nullptr, nullptr, nullptr, 0);
    }
}

// round 13
// speedup vs baseline: 1.8205x; 1.2323x over previous
#include <cuda_runtime.h>
#include <cuda_fp16.h>
#include <math.h>
#include <stdint.h>

// ---------------- problem dims ----------------
constexpr int cB   = 2;
constexpr int cS   = 2048;
constexpr int cE   = 2048;
constexpr int cH   = 2688;
constexpr int c2H  = 2 * cH;
constexpr int cNH  = 4;
constexpr int cDH  = 672;
constexpr int cKS  = 4;
constexpr int cNPH = 672;
constexpr long long cBS  = (long long)cB * cS;        // 4096
constexpr long long cBSH = cBS * cH;
constexpr long long cSCORES = (long long)cB * cNH * cS * cS;
constexpr int cBHS = cB * cNH * cS;
constexpr int c3H  = 3 * cH;
constexpr int cHALF = c3H / 2;

// ---------------- device scratch ----------------
__device__ float  g_xmz[cBS * (long long)c2H];
__device__ float  g_xca[cBSH];
__device__ float  g_h  [cBSH];
__device__ __half g_xh  [cBS * (long long)cE];
__device__ __half g_WinH [(long long)cE * c2H];
__device__ __half g_WoutH[(long long)cH * cE];
__device__ __half g_qh [cBSH];
__device__ __half g_kh [cBSH];
__device__ __half g_vh [cBSH];
__device__ __half g_hsH[cBSH];
__device__ __half g_scoresH[cSCORES];
__device__ float g_ipre[cBHS];
__device__ float g_fpre[cBHS];
__device__ float g_cs  [cBHS];
__device__ float g_a   [cBHS];
__device__ float g_pm  [cBHS];
__device__ float g_rs  [cBHS];
__device__ float g_nsum[cBHS];

// ---------------- helpers ----------------
__device__ __forceinline__ void cp16(uint32_t saddr, const void* gptr, int bytes) {
    asm volatile("cp.async.cg.shared.global [%0], [%1], 16, %2;\n"
                 :: "r"(saddr), "l"(gptr), "r"(bytes));
}
__device__ __forceinline__ void cp_commit() { asm volatile("cp.async.commit_group;\n" ::: "memory"); }
__device__ __forceinline__ void cp_wait0()  { asm volatile("cp.async.wait_group 0;\n" ::: "memory"); }

#define MMA_F16(d, a, b)                                                       \
    asm volatile(                                                              \
        "mma.sync.aligned.m16n8k16.row.col.f32.f16.f16.f32 "                   \
        "{%0,%1,%2,%3},{%4,%5,%6,%7},{%8,%9},{%0,%1,%2,%3};\n"                 \
        : "+f"(d[0]), "+f"(d[1]), "+f"(d[2]), "+f"(d[3])                       \
        : "r"(a[0]), "r"(a[1]), "r"(a[2]), "r"(a[3]), "r"(b[0]), "r"(b[1]))

// ---------------- fp16 GEMM, half operands in gmem and smem ----------------
// C[M,N] = epilogue(A@B). A half row-major MxK. B half: KxN (NN) or NxK (NT).
// mode 0: C(float) = alpha*acc
// mode 1: C(half) scores epilogue + causal row sums into p3; masked tiles skip
// mode 2: C(float) = acc * p1[m]; Kend = tileM+128
#define BM 128
#define BN 128
#define BK 16
#define ASTRH 24     // halves per A/NT-B row (16 + 8 pad)
#define BSTRH 136    // halves per NN-B row

__global__ __launch_bounds__(256)
void tgemm_kernel(int M, int N, int K,
                  const __half* __restrict__ A, int lda, long long sAb, long long sAn,
                  const __half* __restrict__ B, int ldb, long long sBb, long long sBn,
                  void* __restrict__ Cv, int ldc, long long sCb, long long sCn,
                  int nhd, int transB, int mode, float alpha,
                  const float* __restrict__ p1, const float* __restrict__ p2,
                  float* __restrict__ p3, int pstr)
{
    const int z  = blockIdx.z;
    const int zb = z / nhd, zn = z % nhd;
    A += zb * sAb + zn * sAn;
    B += zb * sBb + zn * sBn;

    const int tileM = blockIdx.y * BM;
    const int tileN = blockIdx.x * BN;
    if (mode == 1 && tileN > tileM + BM - 1) return;

    const int t    = threadIdx.x;
    const int lane = t & 31;
    const int warp = t >> 5;
    const int g    = lane >> 2;
    const int t4   = lane & 3;
    const int wm   = (warp & 1) * 64;
    const int wn   = (warp >> 1) * 32;

    __shared__ __half As[2][BM * ASTRH];   // 6 KB each
    __shared__ __half Bs[2][BM * ASTRH];   // NT: 128*24; NN: 16*136=2176 fits

    float acc[4][4][4];
#pragma unroll
    for (int i = 0; i < 4; i++)
#pragma unroll
        for (int j = 0; j < 4; j++)
#pragma unroll
            for (int r = 0; r < 4; r++) acc[i][j][r] = 0.f;

    int Kend = K;
    if (mode == 2) { int lim = tileM + BM; Kend = lim < K ? lim : K; }
    const int nIter = Kend / BK;

    uint32_t sA[2], sB[2];
    sA[0] = (uint32_t)__cvta_generic_to_shared(&As[0][0]);
    sA[1] = (uint32_t)__cvta_generic_to_shared(&As[1][0]);
    sB[0] = (uint32_t)__cvta_generic_to_shared(&Bs[0][0]);
    sB[1] = (uint32_t)__cvta_generic_to_shared(&Bs[1][0]);

    auto loadTiles = [&](int stg, int k0) {
        // A: 128 rows x 16 halves = 2 x 16B per row = 256 chunks
        {
            int row = t >> 1;
            int kc  = (t & 1) * 8;
            const __half* gp = &A[(long long)(tileM + row) * lda + k0 + kc];
            cp16(sA[stg] + (row * ASTRH + kc) * 2, gp, 16);
        }
        if (!transB) {
            // B: 16 rows x 128 halves = 16 chunks/row = 256 chunks
            int kr = t >> 4;
            int n8 = (t & 15) * 8;
            int gn = tileN + n8;
            int ok = (gn < N);
            const __half* gp = &B[(long long)(k0 + kr) * ldb + (ok ? gn : 0)];
            cp16(sB[stg] + (kr * BSTRH + n8) * 2, gp, ok ? 16 : 0);
        } else {
            int row = t >> 1;
            int kc  = (t & 1) * 8;
            const __half* gp = &B[(long long)(tileN + row) * ldb + k0 + kc];
            cp16(sB[stg] + (row * ASTRH + kc) * 2, gp, 16);
        }
        cp_commit();
    };

    loadTiles(0, 0);
    cp_wait0();
    __syncthreads();

    for (int it = 0; it < nIter; it++) {
        const int s  = it & 1;
        const int kn = (it + 1) * BK;
        const bool more = (kn < Kend);
        if (more) loadTiles(s ^ 1, kn);

        const __half* Asb = As[s];
        const __half* Bsb = Bs[s];

        uint32_t af[4][4], bf[4][2];
#pragma unroll
        for (int i = 0; i < 4; i++) {
            int m0 = wm + i * 16 + g;
            const __half* r0 = &Asb[(m0    ) * ASTRH];
            const __half* r1 = &Asb[(m0 + 8) * ASTRH];
            af[i][0] = *reinterpret_cast<const uint32_t*>(r0 + 2 * t4);
            af[i][1] = *reinterpret_cast<const uint32_t*>(r1 + 2 * t4);
            af[i][2] = *reinterpret_cast<const uint32_t*>(r0 + 2 * t4 + 8);
            af[i][3] = *reinterpret_cast<const uint32_t*>(r1 + 2 * t4 + 8);
        }
#pragma unroll
        for (int j = 0; j < 4; j++) {
            int n0 = wn + j * 8 + g;
            if (transB) {
                const __half* rb = &Bsb[n0 * ASTRH];
                bf[j][0] = *reinterpret_cast<const uint32_t*>(rb + 2 * t4);
                bf[j][1] = *reinterpret_cast<const uint32_t*>(rb + 2 * t4 + 8);
            } else {
                __half b0 = Bsb[(2 * t4    ) * BSTRH + n0];
                __half b1 = Bsb[(2 * t4 + 1) * BSTRH + n0];
                __half b2 = Bsb[(2 * t4 + 8) * BSTRH + n0];
                __half b3 = Bsb[(2 * t4 + 9) * BSTRH + n0];
                __half2 p0 = __halves2half2(b0, b1);
                __half2 p1h = __halves2half2(b2, b3);
                bf[j][0] = *reinterpret_cast<uint32_t*>(&p0);
                bf[j][1] = *reinterpret_cast<uint32_t*>(&p1h);
            }
        }
#pragma unroll
        for (int i = 0; i < 4; i++)
#pragma unroll
            for (int j = 0; j < 4; j++)
                MMA_F16(acc[i][j], af[i], bf[j]);

        if (more) cp_wait0();
        __syncthreads();
    }

    // ---- epilogue ----
    const long long zoff = (long long)z * pstr;
    float* Cf  = (float*)Cv;
    __half* Ch = (__half*)Cv;
    if (mode == 1) Ch += zb * sCb + zn * sCn;
    else           Cf += zb * sCb + zn * sCn;

    float p1v[8];
    if (mode == 1) {
#pragma unroll
        for (int j = 0; j < 4; j++) {
            int gn = tileN + wn + j * 8 + t4 * 2;
            p1v[2 * j]     = p1[zoff + gn];
            p1v[2 * j + 1] = p1[zoff + gn + 1];
        }
    }
#pragma unroll
    for (int i = 0; i < 4; i++) {
        int gmBase = tileM + wm + i * 16 + g;
#pragma unroll
        for (int half = 0; half < 2; half++) {
            int gm = gmBase + half * 8;
            float pmv = 0.f, rsv = 1.f;
            if (mode == 1)      pmv = p2[zoff + gm];
            else if (mode == 2) rsv = p1[zoff + gm];
            float rsum = 0.f;
#pragma unroll
            for (int j = 0; j < 4; j++) {
                int gn = tileN + wn + j * 8 + t4 * 2;
                if (gn >= N) continue;
                float v0 = acc[i][j][half * 2 + 0];
                float v1 = acc[i][j][half * 2 + 1];
                if (mode == 1) {
                    v0 = (gn     <= gm) ? v0 * alpha * __expf(p1v[2 * j    ] - pmv) : 0.f;
                    v1 = (gn + 1 <= gm) ? v1 * alpha * __expf(p1v[2 * j + 1] - pmv) : 0.f;
                    rsum += v0 + v1;
                    __half2 hv = __floats2half2_rn(v0, v1);
                    *reinterpret_cast<__half2*>(&Ch[(long long)gm * ldc + gn]) = hv;
                } else if (mode == 2) {
                    v0 *= rsv; v1 *= rsv;
                    *reinterpret_cast<float2*>(&Cf[(long long)gm * ldc + gn]) = make_float2(v0, v1);
                } else {
                    v0 *= alpha; v1 *= alpha;
                    *reinterpret_cast<float2*>(&Cf[(long long)gm * ldc + gn]) = make_float2(v0, v1);
                }
            }
            if (mode == 1) {
                rsum += __shfl_xor_sync(0xffffffffu, rsum, 1);
                rsum += __shfl_xor_sync(0xffffffffu, rsum, 2);
                if (t4 == 0) atomicAdd(&p3[zoff + gm], rsum);
            }
        }
    }
}

// ---------------- fp32 -> fp16 convert ----------------
__global__ void cvth_kernel(const float* __restrict__ in, __half* __restrict__ out,
                            long long n)
{
    long long i = ((long long)blockIdx.x * blockDim.x + threadIdx.x) * 8;
    if (i >= n) return;
    float4 a = *reinterpret_cast<const float4*>(in + i);
    float4 b = *reinterpret_cast<const float4*>(in + i + 4);
    __half2 h0 = __floats2half2_rn(a.x, a.y);
    __half2 h1 = __floats2half2_rn(a.z, a.w);
    __half2 h2 = __floats2half2_rn(b.x, b.y);
    __half2 h3 = __floats2half2_rn(b.z, b.w);
    uint2 pk0 = make_uint2(*reinterpret_cast<uint32_t*>(&h0), *reinterpret_cast<uint32_t*>(&h1));
    uint2 pk1 = make_uint2(*reinterpret_cast<uint32_t*>(&h2), *reinterpret_cast<uint32_t*>(&h3));
    *reinterpret_cast<uint2*>(out + i)     = pk0;
    *reinterpret_cast<uint2*>(out + i + 4) = pk1;
}

// ---------------- fused depthwise conv + SiLU + headwise q/k/v -------------
__global__ void convhead_kernel(const float* __restrict__ xmz,
                                const float* __restrict__ w,
                                const float* __restrict__ bias,
                                const float* __restrict__ Wq,
                                const float* __restrict__ Wk,
                                const float* __restrict__ Wv,
                                float* __restrict__ xca,
                                __half* __restrict__ qh,
                                __half* __restrict__ kh,
                                __half* __restrict__ vh)
{
    long long idx = (long long)blockIdx.x * blockDim.x + threadIdx.x;
    long long total = cBS * (long long)cNPH;
    if (idx >= total) return;
    int p = (int)(idx % cNPH);
    long long bs = idx / cNPH;
    int s = (int)(bs % cS);
    int col = p * 4;

    float4 xr[cKS];
#pragma unroll
    for (int tt = 0; tt < cKS; tt++) {
        int sp = s - (cKS - 1) + tt;
        if (sp >= 0)
            xr[tt] = *reinterpret_cast<const float4*>(xmz + (bs - (cKS - 1) + tt) * c2H + col);
        else
            xr[tt] = make_float4(0.f, 0.f, 0.f, 0.f);
    }
    float4 wt[cKS];
#pragma unroll
    for (int tt = 0; tt < cKS; tt++)
        wt[tt] = *reinterpret_cast<const float4*>(w + tt * cH + col);
    float4 bb = *reinterpret_cast<const float4*>(bias + col);

    float4 xc;
    xc.x = bb.x + xr[0].x*wt[0].x + xr[1].x*wt[1].x + xr[2].x*wt[2].x + xr[3].x*wt[3].x;
    xc.y = bb.y + xr[0].y*wt[0].y + xr[1].y*wt[1].y + xr[2].y*wt[2].y + xr[3].y*wt[3].y;
    xc.z = bb.z + xr[0].z*wt[0].z + xr[1].z*wt[1].z + xr[2].z*wt[2].z + xr[3].z*wt[3].z;
    xc.w = bb.w + xr[0].w*wt[0].w + xr[1].w*wt[1].w + xr[2].w*wt[2].w + xr[3].w*wt[3].w;
    xc.x = xc.x / (1.f + __expf(-xc.x));
    xc.y = xc.y / (1.f + __expf(-xc.y));
    xc.z = xc.z / (1.f + __expf(-xc.z));
    xc.w = xc.w / (1.f + __expf(-xc.w));

    long long base = bs * cH + col;
    *reinterpret_cast<float4*>(xca + base) = xc;

    float4 xv = xr[cKS - 1];

    const float4* wq4 = reinterpret_cast<const float4*>(Wq + p * 16);
    const float4* wk4 = reinterpret_cast<const float4*>(Wk + p * 16);
    const float4* wv4 = reinterpret_cast<const float4*>(Wv + p * 16);
    float4 q0 = wq4[0], q1 = wq4[1], q2 = wq4[2], q3 = wq4[3];
    float4 k0 = wk4[0], k1 = wk4[1], k2 = wk4[2], k3 = wk4[3];
    float4 v0 = wv4[0], v1 = wv4[1], v2 = wv4[2], v3 = wv4[3];
    float4 qo, ko, vo;
    qo.x = xc.x*q0.x + xc.y*q1.x + xc.z*q2.x + xc.w*q3.x;
    qo.y = xc.x*q0.y + xc.y*q1.y + xc.z*q2.y + xc.w*q3.y;
    qo.z = xc.x*q0.z + xc.y*q1.z + xc.z*q2.z + xc.w*q3.z;
    qo.w = xc.x*q0.w + xc.y*q1.w + xc.z*q2.w + xc.w*q3.w;
    ko.x = xc.x*k0.x + xc.y*k1.x + xc.z*k2.x + xc.w*k3.x;
    ko.y = xc.x*k0.y + xc.y*k1.y + xc.z*k2.y + xc.w*k3.y;
    ko.z = xc.x*k0.z + xc.y*k1.z + xc.z*k2.z + xc.w*k3.z;
    ko.w = xc.x*k0.w + xc.y*k1.w + xc.z*k2.w + xc.w*k3.w;
    vo.x = xv.x*v0.x + xv.y*v1.x + xv.z*v2.x + xv.w*v3.x;
    vo.y = xv.x*v0.y + xv.y*v1.y + xv.z*v2.y + xv.w*v3.y;
    vo.z = xv.x*v0.z + xv.y*v1.z + xv.z*v2.z + xv.w*v3.z;
    vo.w = xv.x*v0.w + xv.y*v1.w + xv.z*v2.w + xv.w*v3.w;

    __half2 qh0 = __floats2half2_rn(qo.x, qo.y), qh1 = __floats2half2_rn(qo.z, qo.w);
    __half2 kh0 = __floats2half2_rn(ko.x, ko.y), kh1 = __floats2half2_rn(ko.z, ko.w);
    __half2 vh0 = __floats2half2_rn(vo.x, vo.y), vh1 = __floats2half2_rn(vo.z, vo.w);
    *reinterpret_cast<uint2*>(qh + base) = make_uint2(*reinterpret_cast<uint32_t*>(&qh0),
                                                      *reinterpret_cast<uint32_t*>(&qh1));
    *reinterpret_cast<uint2*>(kh + base) = make_uint2(*reinterpret_cast<uint32_t*>(&kh0),
                                                      *reinterpret_cast<uint32_t*>(&kh1));
    *reinterpret_cast<uint2*>(vh + base) = make_uint2(*reinterpret_cast<uint32_t*>(&vh0),
                                                      *reinterpret_cast<uint32_t*>(&vh1));
}

// ---------------- gates (reads half q/k/v) ----------------
__global__ __launch_bounds__(256)
void gates_kernel(const __half* __restrict__ q, const __half* __restrict__ k,
                  const __half* __restrict__ v,
                  const float* __restrict__ Wig, const float* __restrict__ big,
                  const float* __restrict__ Wfg, const float* __restrict__ bfg,
                  float* __restrict__ ipre, float* __restrict__ fpre)
{
    const int warp = threadIdx.x >> 5;
    const int lane = threadIdx.x & 31;
    const int rw   = warp >> 1;
    const int half = warp & 1;
    const long long row = (long long)blockIdx.x * 4 + rw;

    float ai[4] = {0, 0, 0, 0}, af[4] = {0, 0, 0, 0};
    const int rbeg = half * cHALF;
    const int rend = rbeg + cHALF;
    const long long rbase = row * cH;

    for (int r = rbeg + lane; r < rend; r += 32) {
        float4 wi = *reinterpret_cast<const float4*>(Wig + (long long)r * 4);
        float4 wf = *reinterpret_cast<const float4*>(Wfg + (long long)r * 4);
        float val;
        if (r < cH)          val = __half2float(q[rbase + r]);
        else if (r < 2 * cH) val = __half2float(k[rbase + r - cH]);
        else                 val = __half2float(v[rbase + r - 2 * cH]);
        ai[0] += val * wi.x; ai[1] += val * wi.y;
        ai[2] += val * wi.z; ai[3] += val * wi.w;
        af[0] += val * wf.x; af[1] += val * wf.y;
        af[2] += val * wf.z; af[3] += val * wf.w;
    }

#pragma unroll
    for (int o = 16; o > 0; o >>= 1) {
#pragma unroll
        for (int n = 0; n < 4; n++) {
            ai[n] += __shfl_xor_sync(0xffffffffu, ai[n], o);
            af[n] += __shfl_xor_sync(0xffffffffu, af[n], o);
        }
    }

    __shared__ float part[4][8];
    if (half == 1 && lane == 0) {
#pragma unroll
        for (int n = 0; n < 4; n++) { part[rw][n] = ai[n]; part[rw][4 + n] = af[n]; }
    }
    __syncthreads();
    if (half == 0 && lane == 0) {
        int b = (int)(row / cS), s = (int)(row % cS);
#pragma unroll
        for (int n = 0; n < 4; n++) {
            ipre[(long long)(b * cNH + n) * cS + s] = ai[n] + part[rw][n]     + big[n];
            fpre[(long long)(b * cNH + n) * cS + s] = af[n] + part[rw][4 + n] + bfg[n];
        }
    }
}

// ---------------- scan ----------------
__global__ __launch_bounds__(256)
void scan_kernel(const float* __restrict__ ipre, const float* __restrict__ fpre,
                 float* __restrict__ cs, float* __restrict__ aArr,
                 float* __restrict__ pm, float* __restrict__ nsum)
{
    int bh = blockIdx.x;
    int t  = threadIdx.x;
    const float* fp = fpre + (long long)bh * cS;
    const float* ip = ipre + (long long)bh * cS;

    float loc[8];
    float sum = 0.f;
#pragma unroll
    for (int u = 0; u < 8; u++) {
        int j = t * 8 + u;
        float f = fp[j];
        float lf = fminf(f, 0.f) - log1pf(expf(-fabsf(f)));
        sum += lf;
        loc[u] = sum;
    }
    __shared__ float part[256];
    part[t] = sum;
    __syncthreads();
    for (int off = 1; off < 256; off <<= 1) {
        float vv = (t >= off) ? part[t - off] : 0.f;
        __syncthreads();
        part[t] += vv;
        __syncthreads();
    }
    float excl = part[t] - sum;

    float lmax[8];
    float amax = -1e30f;
#pragma unroll
    for (int u = 0; u < 8; u++) {
        int j = t * 8 + u;
        float csj = excl + loc[u];
        cs[(long long)bh * cS + j] = csj;
        float aj = ip[j] - csj;
        aArr[(long long)bh * cS + j] = aj;
        nsum[(long long)bh * cS + j] = 0.f;
        amax = fmaxf(amax, aj);
        lmax[u] = amax;
    }
    __syncthreads();
    part[t] = amax;
    __syncthreads();
    for (int off = 1; off < 256; off <<= 1) {
        float vv = (t >= off) ? part[t - off] : -1e30f;
        __syncthreads();
        part[t] = fmaxf(part[t], vv);
        __syncthreads();
    }
    float exmax = (t > 0) ? part[t - 1] : -1e30f;
#pragma unroll
    for (int u = 0; u < 8; u++) {
        int j = t * 8 + u;
        pm[(long long)bh * cS + j] = fmaxf(exmax, lmax[u]);
    }
}

// ---------------- finalize n -> rs ----------------
__global__ void nfin_kernel(const float* __restrict__ nsum,
                            const float* __restrict__ cs, const float* __restrict__ pm,
                            float* __restrict__ rs)
{
    int idx = blockIdx.x * blockDim.x + threadIdx.x;
    if (idx >= cBHS) return;
    float m = cs[idx] + pm[idx];
    float n = fmaxf(fabsf(nsum[idx]), __expf(-m));
    rs[idx] = 1.f / (n + 1e-6f);
}

// ---------------- multi-head LN + skip + z-gate (writes half hs) -----------
__global__ __launch_bounds__(256)
void ln_kernel(const float* __restrict__ hbuf, const float* __restrict__ xca,
               const float* __restrict__ xmz, const float* __restrict__ norm_w,
               const float* __restrict__ skip, __half* __restrict__ hsH)
{
    int s  = blockIdx.x;
    int bh = blockIdx.y;
    int t  = threadIdx.x;
    int b = bh / cNH, n = bh % cNH;
    const float* hrow = hbuf + ((long long)bh * cS + s) * cDH;

    float sum = 0.f, ss = 0.f;
    for (int d = t; d < cDH; d += 256) {
        float v = hrow[d];
        sum += v; ss += v * v;
    }
    __shared__ float r1[256], r2[256];
    r1[t] = sum; r2[t] = ss;
    __syncthreads();
    for (int o = 128; o > 0; o >>= 1) {
        if (t < o) { r1[t] += r1[t + o]; r2[t] += r2[t + o]; }
        __syncthreads();
    }
    float mean = r1[0] / cDH;
    float var  = r2[0] / cDH - mean * mean;
    float inv  = rsqrtf(var + 1e-5f);

    long long bsRow = (long long)b * cS + s;
    long long xbase = bsRow * cH;
    long long zbase = bsRow * c2H + cH;
    for (int d = t; d < cDH; d += 256) {
        int col = n * cDH + d;
        float hn = (hrow[d] - mean) * inv * norm_w[col];
        float hk = hn + skip[col] * xca[xbase + col];
        float zv = xmz[zbase + col];
        float sz = zv / (1.f + __expf(-zv));
        hsH[xbase + col] = __float2half(hk * sz);
    }
}

// ---------------- launch ----------------
extern "C" void kernel_launch(void* const* d_in, const int* in_sizes, int n_in,
                              void* d_out, int out_size)
{
    const float* x      = (const float*)d_in[0];
    const float* W_in   = (const float*)d_in[1];
    const float* conv_w = (const float*)d_in[2];
    const float* conv_b = (const float*)d_in[3];
    const float* Wq     = (const float*)d_in[4];
    const float* Wk     = (const float*)d_in[5];
    const float* Wv     = (const float*)d_in[6];
    const float* W_ig   = (const float*)d_in[7];
    const float* b_ig   = (const float*)d_in[8];
    const float* W_fg   = (const float*)d_in[9];
    const float* b_fg   = (const float*)d_in[10];
    const float* norm_w = (const float*)d_in[11];
    const float* skip   = (const float*)d_in[12];
    const float* W_out  = (const float*)d_in[13];
    float* out = (float*)d_out;

    float *p_xmz, *p_xca, *p_h;
    float *p_ipre, *p_fpre, *p_cs, *p_a, *p_pm, *p_rs, *p_ns;
    __half *p_xh, *p_WinH, *p_WoutH, *p_qh, *p_kh, *p_vh, *p_hsH, *p_scH;
    cudaGetSymbolAddress((void**)&p_xmz, g_xmz);
    cudaGetSymbolAddress((void**)&p_xca, g_xca);
    cudaGetSymbolAddress((void**)&p_h,   g_h);
    cudaGetSymbolAddress((void**)&p_xh,  g_xh);
    cudaGetSymbolAddress((void**)&p_WinH, g_WinH);
    cudaGetSymbolAddress((void**)&p_WoutH, g_WoutH);
    cudaGetSymbolAddress((void**)&p_qh,  g_qh);
    cudaGetSymbolAddress((void**)&p_kh,  g_kh);
    cudaGetSymbolAddress((void**)&p_vh,  g_vh);
    cudaGetSymbolAddress((void**)&p_hsH, g_hsH);
    cudaGetSymbolAddress((void**)&p_scH, g_scoresH);
    cudaGetSymbolAddress((void**)&p_ipre, g_ipre);
    cudaGetSymbolAddress((void**)&p_fpre, g_fpre);
    cudaGetSymbolAddress((void**)&p_cs,  g_cs);
    cudaGetSymbolAddress((void**)&p_a,   g_a);
    cudaGetSymbolAddress((void**)&p_pm,  g_pm);
    cudaGetSymbolAddress((void**)&p_rs,  g_rs);
    cudaGetSymbolAddress((void**)&p_ns,  g_nsum);

    const int M0 = (int)cBS;  // 4096

    // 0) fp16 conversions: x, W_in, W_out
    {
        long long nx = cBS * (long long)cE;
        cvth_kernel<<<(int)((nx / 8 + 255) / 256), 256>>>(x, p_xh, nx);
        long long nw = (long long)cE * c2H;
        cvth_kernel<<<(int)((nw / 8 + 255) / 256), 256>>>(W_in, p_WinH, nw);
        long long no = (long long)cH * cE;
        cvth_kernel<<<(int)((no / 8 + 255) / 256), 256>>>(W_out, p_WoutH, no);
    }

    // 1) xh @ WinH -> xmz (fp32 out, merged N = 2H)
    {
        dim3 grid(c2H / BN, M0 / BM, 1);
        tgemm_kernel<<<grid, 256>>>(M0, c2H, cE,
            p_xh, cE, 0, 0,
            p_WinH, c2H, 0, 0,
            p_xmz, c2H, 0, 0,
            1, 0, 0, 1.0f, nullptr, nullptr, nullptr, 0);
    }

    // 2+3) fused conv + SiLU + headwise -> xca fp32, q/k/v fp16
    {
        long long total = cBS * (long long)cNPH;
        int blocks = (int)((total + 255) / 256);
        convhead_kernel<<<blocks, 256>>>(p_xmz, conv_w, conv_b, Wq, Wk, Wv,
                                         p_xca, p_qh, p_kh, p_vh);
    }

    // 4) gates
    gates_kernel<<<M0 / 4, 256>>>(p_qh, p_kh, p_vh, W_ig, b_ig, W_fg, b_fg, p_ipre, p_fpre);

    // 5) scan (also zeroes nsum)
    scan_kernel<<<cB * cNH, 256>>>(p_ipre, p_fpre, p_cs, p_a, p_pm, p_ns);

    // 6) scores (mode 1, half out, fused row sums, causal tile skip)
    {
        dim3 grid(cS / BN, cS / BM, cB * cNH);
        float alpha = 1.0f / sqrtf((float)cDH);
        tgemm_kernel<<<grid, 256>>>(cS, cS, cDH,
            p_qh, cH, (long long)cS * cH, (long long)cDH,
            p_kh, cH, (long long)cS * cH, (long long)cDH,
            p_scH, cS, (long long)cNH * cS * cS, (long long)cS * cS,
            cNH, 1, 1, alpha, p_a, p_pm, p_ns, cS);
    }

    // 7) finalize rs
    nfin_kernel<<<(cBHS + 255) / 256, 256>>>(p_ns, p_cs, p_pm, p_rs);

    // 8) h = diag(rs) * scoresH @ vh (mode 2, causal K-limit, fp32 out)
    {
        dim3 grid((cDH + BN - 1) / BN, cS / BM, cB * cNH);
        tgemm_kernel<<<grid, 256>>>(cS, cDH, cS,
            p_scH, cS, (long long)cNH * cS * cS, (long long)cS * cS,
            p_vh, cH, (long long)cS * cH, (long long)cDH,
            p_h, cDH, (long long)cNH * cS * cDH, (long long)cS * cDH,
            cNH, 0, 2, 1.0f, p_rs, nullptr, nullptr, cS);
    }

    // 9) LN + skip + z gate -> hs fp16
    {
        dim3 grid(cS, cB * cNH);
        ln_kernel<<<grid, 256>>>(p_h, p_xca, p_xmz, norm_w, skip, p_hsH);
    }

    // 10) out = hsH @ WoutH (fp32 out)
    {
        dim3 grid(cE / BN, M0 / BM, 1);
        tgemm_kernel<<<grid, 256>>>(M0, cE, cH,
            p_hsH, cH, 0, 0,
            p_WoutH, cE, 0, 0,
            out, cE, 0, 0,
            1, 0, 0, 1.0f, nullptr, nullptr, nullptr, 0);
    }
}

// round 14
// speedup vs baseline: 2.5680x; 1.4106x over previous
#include <cuda_runtime.h>
#include <cuda_fp16.h>
#include <math.h>
#include <stdint.h>

// ---------------- problem dims ----------------
constexpr int cB   = 2;
constexpr int cS   = 2048;
constexpr int cE   = 2048;
constexpr int cH   = 2688;
constexpr int c2H  = 2 * cH;
constexpr int cNH  = 4;
constexpr int cDH  = 672;
constexpr int cKS  = 4;
constexpr int cNPH = 672;
constexpr long long cBS  = (long long)cB * cS;        // 4096
constexpr long long cBSH = cBS * cH;
constexpr long long cSCORES = (long long)cB * cNH * cS * cS;
constexpr int cBHS = cB * cNH * cS;
constexpr int c3H  = 3 * cH;
constexpr int cHALF = c3H / 2;

// ---------------- device scratch ----------------
__device__ float  g_xmz[cBS * (long long)c2H];
__device__ float  g_xca[cBSH];
__device__ float  g_h  [cBSH];
__device__ __half g_xh  [cBS * (long long)cE];
__device__ __half g_WinH [(long long)cE * c2H];
__device__ __half g_WoutH[(long long)cH * cE];
__device__ __half g_qh [cBSH];
__device__ __half g_kh [cBSH];
__device__ __half g_vh [cBSH];
__device__ __half g_hsH[cBSH];
__device__ __half g_scoresH[cSCORES];
__device__ float g_ipre[cBHS];
__device__ float g_fpre[cBHS];
__device__ float g_cs  [cBHS];
__device__ float g_a   [cBHS];
__device__ float g_pm  [cBHS];
__device__ float g_rs  [cBHS];
__device__ float g_nsum[cBHS];

// ---------------- helpers ----------------
__device__ __forceinline__ void cp16(uint32_t saddr, const void* gptr, int bytes) {
    asm volatile("cp.async.cg.shared.global [%0], [%1], 16, %2;\n"
                 :: "r"(saddr), "l"(gptr), "r"(bytes));
}
__device__ __forceinline__ void cp_commit() { asm volatile("cp.async.commit_group;\n" ::: "memory"); }
__device__ __forceinline__ void cp_wait0()  { asm volatile("cp.async.wait_group 0;\n" ::: "memory"); }

__device__ __forceinline__ void ldsm4(uint32_t& r0, uint32_t& r1, uint32_t& r2, uint32_t& r3,
                                      uint32_t a) {
    asm volatile("ldmatrix.sync.aligned.m8n8.x4.shared.b16 {%0,%1,%2,%3}, [%4];"
                 : "=r"(r0), "=r"(r1), "=r"(r2), "=r"(r3) : "r"(a));
}
__device__ __forceinline__ void ldsm4t(uint32_t& r0, uint32_t& r1, uint32_t& r2, uint32_t& r3,
                                       uint32_t a) {
    asm volatile("ldmatrix.sync.aligned.m8n8.x4.trans.shared.b16 {%0,%1,%2,%3}, [%4];"
                 : "=r"(r0), "=r"(r1), "=r"(r2), "=r"(r3) : "r"(a));
}

#define MMA_F16(d, a, b)                                                       \
    asm volatile(                                                              \
        "mma.sync.aligned.m16n8k16.row.col.f32.f16.f16.f32 "                   \
        "{%0,%1,%2,%3},{%4,%5,%6,%7},{%8,%9},{%0,%1,%2,%3};\n"                 \
        : "+f"(d[0]), "+f"(d[1]), "+f"(d[2]), "+f"(d[3])                       \
        : "r"(a[0]), "r"(a[1]), "r"(a[2]), "r"(a[3]), "r"(b[0]), "r"(b[1]))

// ---------------- fp16 GEMM: ldmatrix fragments, BK=32 ----------------
// A half row-major MxK. B half: KxN (NN, ldmatrix.trans) or NxK (NT).
// mode 0: C(float) = alpha*acc
// mode 1: C(half) scores epilogue + causal row sums into p3; masked tiles skip
// mode 2: C(float) = acc * p1[m]; Kend = tileM+128
#define BM 128
#define BN 128
#define BK 32
#define ASTRH 40     // halves per A/NT-B row (32 + 8 pad) -> 80B, conflict-free
#define BSTRH 136    // halves per NN-B row -> 272B, conflict-free trans

__global__ __launch_bounds__(256)
void tgemm_kernel(int M, int N, int K,
                  const __half* __restrict__ A, int lda, long long sAb, long long sAn,
                  const __half* __restrict__ B, int ldb, long long sBb, long long sBn,
                  void* __restrict__ Cv, int ldc, long long sCb, long long sCn,
                  int nhd, int transB, int mode, float alpha,
                  const float* __restrict__ p1, const float* __restrict__ p2,
                  float* __restrict__ p3, int pstr)
{
    const int z  = blockIdx.z;
    const int zb = z / nhd, zn = z % nhd;
    A += zb * sAb + zn * sAn;
    B += zb * sBb + zn * sBn;

    const int tileM = blockIdx.y * BM;
    const int tileN = blockIdx.x * BN;
    if (mode == 1 && tileN > tileM + BM - 1) return;

    const int t    = threadIdx.x;
    const int lane = t & 31;
    const int warp = t >> 5;
    const int g    = lane >> 2;
    const int t4   = lane & 3;
    const int wm   = (warp & 1) * 64;
    const int wn   = (warp >> 1) * 32;

    __shared__ __half As[2][BM * ASTRH];   // 10 KB each
    __shared__ __half Bs[2][BM * ASTRH];   // NT: 128*40; NN: 32*136=4352 fits

    float acc[4][4][4];
#pragma unroll
    for (int i = 0; i < 4; i++)
#pragma unroll
        for (int j = 0; j < 4; j++)
#pragma unroll
            for (int r = 0; r < 4; r++) acc[i][j][r] = 0.f;

    int Kend = K;
    if (mode == 2) { int lim = tileM + BM; Kend = lim < K ? lim : K; }
    const int nIter = Kend / BK;

    uint32_t sA[2], sB[2];
    sA[0] = (uint32_t)__cvta_generic_to_shared(&As[0][0]);
    sA[1] = (uint32_t)__cvta_generic_to_shared(&As[1][0]);
    sB[0] = (uint32_t)__cvta_generic_to_shared(&Bs[0][0]);
    sB[1] = (uint32_t)__cvta_generic_to_shared(&Bs[1][0]);

    // ldmatrix per-lane offsets (bytes)
    // A/x4: row = wm + ((lane>>3)&1)*8 + (lane&7); kh = (lane>>4)*8
    const uint32_t aOff = (uint32_t)(((wm + ((lane >> 3) & 1) * 8 + (lane & 7)) * ASTRH
                                      + (lane >> 4) * 8) * 2);
    // NT-B/x4: row = wn + ((lane>>4)&1)*8 + (lane&7); kh = ((lane>>3)&1)*8
    const uint32_t bOffNT = (uint32_t)(((wn + ((lane >> 4) & 1) * 8 + (lane & 7)) * ASTRH
                                        + ((lane >> 3) & 1) * 8) * 2);
    // NN-B/x4.trans: krow = ((lane>>3)&1)*8 + (lane&7); ncol = wn + ((lane>>4)&1)*8
    const uint32_t bOffNN = (uint32_t)(((((lane >> 3) & 1) * 8 + (lane & 7)) * BSTRH
                                        + wn + ((lane >> 4) & 1) * 8) * 2);

    auto loadTiles = [&](int stg, int k0) {
        // A: 128 rows x 32 halves (64B) = 512 chunks
#pragma unroll
        for (int hh = 0; hh < 2; hh++) {
            int c   = t + hh * 256;
            int row = c >> 2;
            int kc  = (c & 3) * 8;
            const __half* gp = &A[(long long)(tileM + row) * lda + k0 + kc];
            cp16(sA[stg] + (row * ASTRH + kc) * 2, gp, 16);
        }
        if (!transB) {
            // B: 32 rows x 128 halves (256B) = 512 chunks
#pragma unroll
            for (int hh = 0; hh < 2; hh++) {
                int c  = t + hh * 256;
                int kr = c >> 4;
                int n8 = (c & 15) * 8;
                int gn = tileN + n8;
                int ok = (gn < N);
                const __half* gp = &B[(long long)(k0 + kr) * ldb + (ok ? gn : 0)];
                cp16(sB[stg] + (kr * BSTRH + n8) * 2, gp, ok ? 16 : 0);
            }
        } else {
#pragma unroll
            for (int hh = 0; hh < 2; hh++) {
                int c   = t + hh * 256;
                int row = c >> 2;
                int kc  = (c & 3) * 8;
                const __half* gp = &B[(long long)(tileN + row) * ldb + k0 + kc];
                cp16(sB[stg] + (row * ASTRH + kc) * 2, gp, 16);
            }
        }
        cp_commit();
    };

    loadTiles(0, 0);
    cp_wait0();
    __syncthreads();

    for (int it = 0; it < nIter; it++) {
        const int s  = it & 1;
        const int kn = (it + 1) * BK;
        const bool more = (kn < Kend);
        if (more) loadTiles(s ^ 1, kn);

        const uint32_t aBase = sA[s];
        const uint32_t bBase = sB[s];

#pragma unroll
        for (int ks = 0; ks < BK; ks += 16) {
            uint32_t af[4][4], bf[4][2];
#pragma unroll
            for (int i = 0; i < 4; i++)
                ldsm4(af[i][0], af[i][1], af[i][2], af[i][3],
                      aBase + aOff + (uint32_t)((i * 16 * ASTRH + ks) * 2));
            if (transB) {
#pragma unroll
                for (int jj = 0; jj < 4; jj += 2)
                    ldsm4(bf[jj][0], bf[jj][1], bf[jj + 1][0], bf[jj + 1][1],
                          bBase + bOffNT + (uint32_t)((jj * 8 * ASTRH + ks) * 2));
            } else {
#pragma unroll
                for (int jj = 0; jj < 4; jj += 2)
                    ldsm4t(bf[jj][0], bf[jj][1], bf[jj + 1][0], bf[jj + 1][1],
                           bBase + bOffNN + (uint32_t)((ks * BSTRH + jj * 8) * 2));
            }
#pragma unroll
            for (int i = 0; i < 4; i++)
#pragma unroll
                for (int j = 0; j < 4; j++)
                    MMA_F16(acc[i][j], af[i], bf[j]);
        }

        if (more) cp_wait0();
        __syncthreads();
    }

    // ---- epilogue ----
    const long long zoff = (long long)z * pstr;
    float* Cf  = (float*)Cv;
    __half* Ch = (__half*)Cv;
    if (mode == 1) Ch += zb * sCb + zn * sCn;
    else           Cf += zb * sCb + zn * sCn;

    float p1v[8];
    if (mode == 1) {
#pragma unroll
        for (int j = 0; j < 4; j++) {
            int gn = tileN + wn + j * 8 + t4 * 2;
            p1v[2 * j]     = p1[zoff + gn];
            p1v[2 * j + 1] = p1[zoff + gn + 1];
        }
    }
#pragma unroll
    for (int i = 0; i < 4; i++) {
        int gmBase = tileM + wm + i * 16 + g;
#pragma unroll
        for (int half = 0; half < 2; half++) {
            int gm = gmBase + half * 8;
            float pmv = 0.f, rsv = 1.f;
            if (mode == 1)      pmv = p2[zoff + gm];
            else if (mode == 2) rsv = p1[zoff + gm];
            float rsum = 0.f;
#pragma unroll
            for (int j = 0; j < 4; j++) {
                int gn = tileN + wn + j * 8 + t4 * 2;
                if (gn >= N) continue;
                float v0 = acc[i][j][half * 2 + 0];
                float v1 = acc[i][j][half * 2 + 1];
                if (mode == 1) {
                    v0 = (gn     <= gm) ? v0 * alpha * __expf(p1v[2 * j    ] - pmv) : 0.f;
                    v1 = (gn + 1 <= gm) ? v1 * alpha * __expf(p1v[2 * j + 1] - pmv) : 0.f;
                    rsum += v0 + v1;
                    __half2 hv = __floats2half2_rn(v0, v1);
                    *reinterpret_cast<__half2*>(&Ch[(long long)gm * ldc + gn]) = hv;
                } else if (mode == 2) {
                    v0 *= rsv; v1 *= rsv;
                    *reinterpret_cast<float2*>(&Cf[(long long)gm * ldc + gn]) = make_float2(v0, v1);
                } else {
                    v0 *= alpha; v1 *= alpha;
                    *reinterpret_cast<float2*>(&Cf[(long long)gm * ldc + gn]) = make_float2(v0, v1);
                }
            }
            if (mode == 1) {
                rsum += __shfl_xor_sync(0xffffffffu, rsum, 1);
                rsum += __shfl_xor_sync(0xffffffffu, rsum, 2);
                if (t4 == 0) atomicAdd(&p3[zoff + gm], rsum);
            }
        }
    }
}

// ---------------- fp32 -> fp16 convert ----------------
__global__ void cvth_kernel(const float* __restrict__ in, __half* __restrict__ out,
                            long long n)
{
    long long i = ((long long)blockIdx.x * blockDim.x + threadIdx.x) * 8;
    if (i >= n) return;
    float4 a = *reinterpret_cast<const float4*>(in + i);
    float4 b = *reinterpret_cast<const float4*>(in + i + 4);
    __half2 h0 = __floats2half2_rn(a.x, a.y);
    __half2 h1 = __floats2half2_rn(a.z, a.w);
    __half2 h2 = __floats2half2_rn(b.x, b.y);
    __half2 h3 = __floats2half2_rn(b.z, b.w);
    uint2 pk0 = make_uint2(*reinterpret_cast<uint32_t*>(&h0), *reinterpret_cast<uint32_t*>(&h1));
    uint2 pk1 = make_uint2(*reinterpret_cast<uint32_t*>(&h2), *reinterpret_cast<uint32_t*>(&h3));
    *reinterpret_cast<uint2*>(out + i)     = pk0;
    *reinterpret_cast<uint2*>(out + i + 4) = pk1;
}

// ---------------- fused depthwise conv + SiLU + headwise q/k/v -------------
__global__ void convhead_kernel(const float* __restrict__ xmz,
                                const float* __restrict__ w,
                                const float* __restrict__ bias,
                                const float* __restrict__ Wq,
                                const float* __restrict__ Wk,
                                const float* __restrict__ Wv,
                                float* __restrict__ xca,
                                __half* __restrict__ qh,
                                __half* __restrict__ kh,
                                __half* __restrict__ vh)
{
    long long idx = (long long)blockIdx.x * blockDim.x + threadIdx.x;
    long long total = cBS * (long long)cNPH;
    if (idx >= total) return;
    int p = (int)(idx % cNPH);
    long long bs = idx / cNPH;
    int s = (int)(bs % cS);
    int col = p * 4;

    float4 xr[cKS];
#pragma unroll
    for (int tt = 0; tt < cKS; tt++) {
        int sp = s - (cKS - 1) + tt;
        if (sp >= 0)
            xr[tt] = *reinterpret_cast<const float4*>(xmz + (bs - (cKS - 1) + tt) * c2H + col);
        else
            xr[tt] = make_float4(0.f, 0.f, 0.f, 0.f);
    }
    float4 wt[cKS];
#pragma unroll
    for (int tt = 0; tt < cKS; tt++)
        wt[tt] = *reinterpret_cast<const float4*>(w + tt * cH + col);
    float4 bb = *reinterpret_cast<const float4*>(bias + col);

    float4 xc;
    xc.x = bb.x + xr[0].x*wt[0].x + xr[1].x*wt[1].x + xr[2].x*wt[2].x + xr[3].x*wt[3].x;
    xc.y = bb.y + xr[0].y*wt[0].y + xr[1].y*wt[1].y + xr[2].y*wt[2].y + xr[3].y*wt[3].y;
    xc.z = bb.z + xr[0].z*wt[0].z + xr[1].z*wt[1].z + xr[2].z*wt[2].z + xr[3].z*wt[3].z;
    xc.w = bb.w + xr[0].w*wt[0].w + xr[1].w*wt[1].w + xr[2].w*wt[2].w + xr[3].w*wt[3].w;
    xc.x = xc.x / (1.f + __expf(-xc.x));
    xc.y = xc.y / (1.f + __expf(-xc.y));
    xc.z = xc.z / (1.f + __expf(-xc.z));
    xc.w = xc.w / (1.f + __expf(-xc.w));

    long long base = bs * cH + col;
    *reinterpret_cast<float4*>(xca + base) = xc;

    float4 xv = xr[cKS - 1];

    const float4* wq4 = reinterpret_cast<const float4*>(Wq + p * 16);
    const float4* wk4 = reinterpret_cast<const float4*>(Wk + p * 16);
    const float4* wv4 = reinterpret_cast<const float4*>(Wv + p * 16);
    float4 q0 = wq4[0], q1 = wq4[1], q2 = wq4[2], q3 = wq4[3];
    float4 k0 = wk4[0], k1 = wk4[1], k2 = wk4[2], k3 = wk4[3];
    float4 v0 = wv4[0], v1 = wv4[1], v2 = wv4[2], v3 = wv4[3];
    float4 qo, ko, vo;
    qo.x = xc.x*q0.x + xc.y*q1.x + xc.z*q2.x + xc.w*q3.x;
    qo.y = xc.x*q0.y + xc.y*q1.y + xc.z*q2.y + xc.w*q3.y;
    qo.z = xc.x*q0.z + xc.y*q1.z + xc.z*q2.z + xc.w*q3.z;
    qo.w = xc.x*q0.w + xc.y*q1.w + xc.z*q2.w + xc.w*q3.w;
    ko.x = xc.x*k0.x + xc.y*k1.x + xc.z*k2.x + xc.w*k3.x;
    ko.y = xc.x*k0.y + xc.y*k1.y + xc.z*k2.y + xc.w*k3.y;
    ko.z = xc.x*k0.z + xc.y*k1.z + xc.z*k2.z + xc.w*k3.z;
    ko.w = xc.x*k0.w + xc.y*k1.w + xc.z*k2.w + xc.w*k3.w;
    vo.x = xv.x*v0.x + xv.y*v1.x + xv.z*v2.x + xv.w*v3.x;
    vo.y = xv.x*v0.y + xv.y*v1.y + xv.z*v2.y + xv.w*v3.y;
    vo.z = xv.x*v0.z + xv.y*v1.z + xv.z*v2.z + xv.w*v3.z;
    vo.w = xv.x*v0.w + xv.y*v1.w + xv.z*v2.w + xv.w*v3.w;

    __half2 qh0 = __floats2half2_rn(qo.x, qo.y), qh1 = __floats2half2_rn(qo.z, qo.w);
    __half2 kh0 = __floats2half2_rn(ko.x, ko.y), kh1 = __floats2half2_rn(ko.z, ko.w);
    __half2 vh0 = __floats2half2_rn(vo.x, vo.y), vh1 = __floats2half2_rn(vo.z, vo.w);
    *reinterpret_cast<uint2*>(qh + base) = make_uint2(*reinterpret_cast<uint32_t*>(&qh0),
                                                      *reinterpret_cast<uint32_t*>(&qh1));
    *reinterpret_cast<uint2*>(kh + base) = make_uint2(*reinterpret_cast<uint32_t*>(&kh0),
                                                      *reinterpret_cast<uint32_t*>(&kh1));
    *reinterpret_cast<uint2*>(vh + base) = make_uint2(*reinterpret_cast<uint32_t*>(&vh0),
                                                      *reinterpret_cast<uint32_t*>(&vh1));
}

// ---------------- gates (reads half q/k/v) ----------------
__global__ __launch_bounds__(256)
void gates_kernel(const __half* __restrict__ q, const __half* __restrict__ k,
                  const __half* __restrict__ v,
                  const float* __restrict__ Wig, const float* __restrict__ big,
                  const float* __restrict__ Wfg, const float* __restrict__ bfg,
                  float* __restrict__ ipre, float* __restrict__ fpre)
{
    const int warp = threadIdx.x >> 5;
    const int lane = threadIdx.x & 31;
    const int rw   = warp >> 1;
    const int half = warp & 1;
    const long long row = (long long)blockIdx.x * 4 + rw;

    float ai[4] = {0, 0, 0, 0}, af[4] = {0, 0, 0, 0};
    const int rbeg = half * cHALF;
    const int rend = rbeg + cHALF;
    const long long rbase = row * cH;

    for (int r = rbeg + lane; r < rend; r += 32) {
        float4 wi = *reinterpret_cast<const float4*>(Wig + (long long)r * 4);
        float4 wf = *reinterpret_cast<const float4*>(Wfg + (long long)r * 4);
        float val;
        if (r < cH)          val = __half2float(q[rbase + r]);
        else if (r < 2 * cH) val = __half2float(k[rbase + r - cH]);
        else                 val = __half2float(v[rbase + r - 2 * cH]);
        ai[0] += val * wi.x; ai[1] += val * wi.y;
        ai[2] += val * wi.z; ai[3] += val * wi.w;
        af[0] += val * wf.x; af[1] += val * wf.y;
        af[2] += val * wf.z; af[3] += val * wf.w;
    }

#pragma unroll
    for (int o = 16; o > 0; o >>= 1) {
#pragma unroll
        for (int n = 0; n < 4; n++) {
            ai[n] += __shfl_xor_sync(0xffffffffu, ai[n], o);
            af[n] += __shfl_xor_sync(0xffffffffu, af[n], o);
        }
    }

    __shared__ float part[4][8];
    if (half == 1 && lane == 0) {
#pragma unroll
        for (int n = 0; n < 4; n++) { part[rw][n] = ai[n]; part[rw][4 + n] = af[n]; }
    }
    __syncthreads();
    if (half == 0 && lane == 0) {
        int b = (int)(row / cS), s = (int)(row % cS);
#pragma unroll
        for (int n = 0; n < 4; n++) {
            ipre[(long long)(b * cNH + n) * cS + s] = ai[n] + part[rw][n]     + big[n];
            fpre[(long long)(b * cNH + n) * cS + s] = af[n] + part[rw][4 + n] + bfg[n];
        }
    }
}

// ---------------- scan ----------------
__global__ __launch_bounds__(256)
void scan_kernel(const float* __restrict__ ipre, const float* __restrict__ fpre,
                 float* __restrict__ cs, float* __restrict__ aArr,
                 float* __restrict__ pm, float* __restrict__ nsum)
{
    int bh = blockIdx.x;
    int t  = threadIdx.x;
    const float* fp = fpre + (long long)bh * cS;
    const float* ip = ipre + (long long)bh * cS;

    float loc[8];
    float sum = 0.f;
#pragma unroll
    for (int u = 0; u < 8; u++) {
        int j = t * 8 + u;
        float f = fp[j];
        float lf = fminf(f, 0.f) - log1pf(expf(-fabsf(f)));
        sum += lf;
        loc[u] = sum;
    }
    __shared__ float part[256];
    part[t] = sum;
    __syncthreads();
    for (int off = 1; off < 256; off <<= 1) {
        float vv = (t >= off) ? part[t - off] : 0.f;
        __syncthreads();
        part[t] += vv;
        __syncthreads();
    }
    float excl = part[t] - sum;

    float lmax[8];
    float amax = -1e30f;
#pragma unroll
    for (int u = 0; u < 8; u++) {
        int j = t * 8 + u;
        float csj = excl + loc[u];
        cs[(long long)bh * cS + j] = csj;
        float aj = ip[j] - csj;
        aArr[(long long)bh * cS + j] = aj;
        nsum[(long long)bh * cS + j] = 0.f;
        amax = fmaxf(amax, aj);
        lmax[u] = amax;
    }
    __syncthreads();
    part[t] = amax;
    __syncthreads();
    for (int off = 1; off < 256; off <<= 1) {
        float vv = (t >= off) ? part[t - off] : -1e30f;
        __syncthreads();
        part[t] = fmaxf(part[t], vv);
        __syncthreads();
    }
    float exmax = (t > 0) ? part[t - 1] : -1e30f;
#pragma unroll
    for (int u = 0; u < 8; u++) {
        int j = t * 8 + u;
        pm[(long long)bh * cS + j] = fmaxf(exmax, lmax[u]);
    }
}

// ---------------- finalize n -> rs ----------------
__global__ void nfin_kernel(const float* __restrict__ nsum,
                            const float* __restrict__ cs, const float* __restrict__ pm,
                            float* __restrict__ rs)
{
    int idx = blockIdx.x * blockDim.x + threadIdx.x;
    if (idx >= cBHS) return;
    float m = cs[idx] + pm[idx];
    float n = fmaxf(fabsf(nsum[idx]), __expf(-m));
    rs[idx] = 1.f / (n + 1e-6f);
}

// ---------------- multi-head LN + skip + z-gate (writes half hs) -----------
__global__ __launch_bounds__(256)
void ln_kernel(const float* __restrict__ hbuf, const float* __restrict__ xca,
               const float* __restrict__ xmz, const float* __restrict__ norm_w,
               const float* __restrict__ skip, __half* __restrict__ hsH)
{
    int s  = blockIdx.x;
    int bh = blockIdx.y;
    int t  = threadIdx.x;
    int b = bh / cNH, n = bh % cNH;
    const float* hrow = hbuf + ((long long)bh * cS + s) * cDH;

    float sum = 0.f, ss = 0.f;
    for (int d = t; d < cDH; d += 256) {
        float v = hrow[d];
        sum += v; ss += v * v;
    }
    __shared__ float r1[256], r2[256];
    r1[t] = sum; r2[t] = ss;
    __syncthreads();
    for (int o = 128; o > 0; o >>= 1) {
        if (t < o) { r1[t] += r1[t + o]; r2[t] += r2[t + o]; }
        __syncthreads();
    }
    float mean = r1[0] / cDH;
    float var  = r2[0] / cDH - mean * mean;
    float inv  = rsqrtf(var + 1e-5f);

    long long bsRow = (long long)b * cS + s;
    long long xbase = bsRow * cH;
    long long zbase = bsRow * c2H + cH;
    for (int d = t; d < cDH; d += 256) {
        int col = n * cDH + d;
        float hn = (hrow[d] - mean) * inv * norm_w[col];
        float hk = hn + skip[col] * xca[xbase + col];
        float zv = xmz[zbase + col];
        float sz = zv / (1.f + __expf(-zv));
        hsH[xbase + col] = __float2half(hk * sz);
    }
}

// ---------------- launch ----------------
extern "C" void kernel_launch(void* const* d_in, const int* in_sizes, int n_in,
                              void* d_out, int out_size)
{
    const float* x      = (const float*)d_in[0];
    const float* W_in   = (const float*)d_in[1];
    const float* conv_w = (const float*)d_in[2];
    const float* conv_b = (const float*)d_in[3];
    const float* Wq     = (const float*)d_in[4];
    const float* Wk     = (const float*)d_in[5];
    const float* Wv     = (const float*)d_in[6];
    const float* W_ig   = (const float*)d_in[7];
    const float* b_ig   = (const float*)d_in[8];
    const float* W_fg   = (const float*)d_in[9];
    const float* b_fg   = (const float*)d_in[10];
    const float* norm_w = (const float*)d_in[11];
    const float* skip   = (const float*)d_in[12];
    const float* W_out  = (const float*)d_in[13];
    float* out = (float*)d_out;

    float *p_xmz, *p_xca, *p_h;
    float *p_ipre, *p_fpre, *p_cs, *p_a, *p_pm, *p_rs, *p_ns;
    __half *p_xh, *p_WinH, *p_WoutH, *p_qh, *p_kh, *p_vh, *p_hsH, *p_scH;
    cudaGetSymbolAddress((void**)&p_xmz, g_xmz);
    cudaGetSymbolAddress((void**)&p_xca, g_xca);
    cudaGetSymbolAddress((void**)&p_h,   g_h);
    cudaGetSymbolAddress((void**)&p_xh,  g_xh);
    cudaGetSymbolAddress((void**)&p_WinH, g_WinH);
    cudaGetSymbolAddress((void**)&p_WoutH, g_WoutH);
    cudaGetSymbolAddress((void**)&p_qh,  g_qh);
    cudaGetSymbolAddress((void**)&p_kh,  g_kh);
    cudaGetSymbolAddress((void**)&p_vh,  g_vh);
    cudaGetSymbolAddress((void**)&p_hsH, g_hsH);
    cudaGetSymbolAddress((void**)&p_scH, g_scoresH);
    cudaGetSymbolAddress((void**)&p_ipre, g_ipre);
    cudaGetSymbolAddress((void**)&p_fpre, g_fpre);
    cudaGetSymbolAddress((void**)&p_cs,  g_cs);
    cudaGetSymbolAddress((void**)&p_a,   g_a);
    cudaGetSymbolAddress((void**)&p_pm,  g_pm);
    cudaGetSymbolAddress((void**)&p_rs,  g_rs);
    cudaGetSymbolAddress((void**)&p_ns,  g_nsum);

    const int M0 = (int)cBS;  // 4096

    // 0) fp16 conversions: x, W_in, W_out
    {
        long long nx = cBS * (long long)cE;
        cvth_kernel<<<(int)((nx / 8 + 255) / 256), 256>>>(x, p_xh, nx);
        long long nw = (long long)cE * c2H;
        cvth_kernel<<<(int)((nw / 8 + 255) / 256), 256>>>(W_in, p_WinH, nw);
        long long no = (long long)cH * cE;
        cvth_kernel<<<(int)((no / 8 + 255) / 256), 256>>>(W_out, p_WoutH, no);
    }

    // 1) xh @ WinH -> xmz (fp32 out, merged N = 2H)
    {
        dim3 grid(c2H / BN, M0 / BM, 1);
        tgemm_kernel<<<grid, 256>>>(M0, c2H, cE,
            p_xh, cE, 0, 0,
            p_WinH, c2H, 0, 0,
            p_xmz, c2H, 0, 0,
            1, 0, 0, 1.0f, nullptr, nullptr, nullptr, 0);
    }

    // 2+3) fused conv + SiLU + headwise -> xca fp32, q/k/v fp16
    {
        long long total = cBS * (long long)cNPH;
        int blocks = (int)((total + 255) / 256);
        convhead_kernel<<<blocks, 256>>>(p_xmz, conv_w, conv_b, Wq, Wk, Wv,
                                         p_xca, p_qh, p_kh, p_vh);
    }

    // 4) gates
    gates_kernel<<<M0 / 4, 256>>>(p_qh, p_kh, p_vh, W_ig, b_ig, W_fg, b_fg, p_ipre, p_fpre);

    // 5) scan (also zeroes nsum)
    scan_kernel<<<cB * cNH, 256>>>(p_ipre, p_fpre, p_cs, p_a, p_pm, p_ns);

    // 6) scores (mode 1, half out, fused row sums, causal tile skip)
    {
        dim3 grid(cS / BN, cS / BM, cB * cNH);
        float alpha = 1.0f / sqrtf((float)cDH);
        tgemm_kernel<<<grid, 256>>>(cS, cS, cDH,
            p_qh, cH, (long long)cS * cH, (long long)cDH,
            p_kh, cH, (long long)cS * cH, (long long)cDH,
            p_scH, cS, (long long)cNH * cS * cS, (long long)cS * cS,
            cNH, 1, 1, alpha, p_a, p_pm, p_ns, cS);
    }

    // 7) finalize rs
    nfin_kernel<<<(cBHS + 255) / 256, 256>>>(p_ns, p_cs, p_pm, p_rs);

    // 8) h = diag(rs) * scoresH @ vh (mode 2, causal K-limit, fp32 out)
    {
        dim3 grid((cDH + BN - 1) / BN, cS / BM, cB * cNH);
        tgemm_kernel<<<grid, 256>>>(cS, cDH, cS,
            p_scH, cS, (long long)cNH * cS * cS, (long long)cS * cS,
            p_vh, cH, (long long)cS * cH, (long long)cDH,
            p_h, cDH, (long long)cNH * cS * cDH, (long long)cS * cDH,
            cNH, 0, 2, 1.0f, p_rs, nullptr, nullptr, cS);
    }

    // 9) LN + skip + z gate -> hs fp16
    {
        dim3 grid(cS, cB * cNH);
        ln_kernel<<<grid, 256>>>(p_h, p_xca, p_xmz, norm_w, skip, p_hsH);
    }

    // 10) out = hsH @ WoutH (fp32 out)
    {
        dim3 grid(cE / BN, M0 / BM, 1);
        tgemm_kernel<<<grid, 256>>>(M0, cE, cH,
            p_hsH, cH, 0, 0,
            p_WoutH, cE, 0, 0,
            out, cE, 0, 0,
            1, 0, 0, 1.0f, nullptr, nullptr, nullptr, 0);
    }
}

// round 15
// speedup vs baseline: 2.6054x; 1.0146x over previous
#include <cuda_runtime.h>
#include <cuda_fp16.h>
#include <math.h>
#include <stdint.h>

// ---------------- problem dims ----------------
constexpr int cB   = 2;
constexpr int cS   = 2048;
constexpr int cE   = 2048;
constexpr int cH   = 2688;
constexpr int c2H  = 2 * cH;
constexpr int cNH  = 4;
constexpr int cDH  = 672;
constexpr int cKS  = 4;
constexpr int cNPH = 672;
constexpr long long cBS  = (long long)cB * cS;        // 4096
constexpr long long cBSH = cBS * cH;
constexpr long long cSCORES = (long long)cB * cNH * cS * cS;
constexpr int cBHS = cB * cNH * cS;
constexpr int c3H  = 3 * cH;
constexpr int cHALF = c3H / 2;

// ---------------- device scratch ----------------
__device__ float  g_xmz[cBS * (long long)c2H];
__device__ float  g_xca[cBSH];
__device__ float  g_h  [cBSH];
__device__ __half g_xh  [cBS * (long long)cE];
__device__ __half g_WinH [(long long)cE * c2H];
__device__ __half g_WoutH[(long long)cH * cE];
__device__ __half g_qh [cBSH];
__device__ __half g_kh [cBSH];
__device__ __half g_vh [cBSH];
__device__ __half g_hsH[cBSH];
__device__ __half g_scoresH[cSCORES];
__device__ float g_ipre[cBHS];
__device__ float g_fpre[cBHS];
__device__ float g_cs  [cBHS];
__device__ float g_a   [cBHS];
__device__ float g_pm  [cBHS];
__device__ float g_rs  [cBHS];
__device__ float g_nsum[cBHS];

// ---------------- helpers ----------------
__device__ __forceinline__ void cp16(uint32_t saddr, const void* gptr, int bytes) {
    asm volatile("cp.async.cg.shared.global [%0], [%1], 16, %2;\n"
                 :: "r"(saddr), "l"(gptr), "r"(bytes));
}
__device__ __forceinline__ void cp_commit() { asm volatile("cp.async.commit_group;\n" ::: "memory"); }
__device__ __forceinline__ void cp_wait0()  { asm volatile("cp.async.wait_group 0;\n" ::: "memory"); }

__device__ __forceinline__ void ldsm4(uint32_t& r0, uint32_t& r1, uint32_t& r2, uint32_t& r3,
                                      uint32_t a) {
    asm volatile("ldmatrix.sync.aligned.m8n8.x4.shared.b16 {%0,%1,%2,%3}, [%4];"
                 : "=r"(r0), "=r"(r1), "=r"(r2), "=r"(r3) : "r"(a));
}
__device__ __forceinline__ void ldsm4t(uint32_t& r0, uint32_t& r1, uint32_t& r2, uint32_t& r3,
                                       uint32_t a) {
    asm volatile("ldmatrix.sync.aligned.m8n8.x4.trans.shared.b16 {%0,%1,%2,%3}, [%4];"
                 : "=r"(r0), "=r"(r1), "=r"(r2), "=r"(r3) : "r"(a));
}

#define MMA_F16(d, a, b)                                                       \
    asm volatile(                                                              \
        "mma.sync.aligned.m16n8k16.row.col.f32.f16.f16.f32 "                   \
        "{%0,%1,%2,%3},{%4,%5,%6,%7},{%8,%9},{%0,%1,%2,%3};\n"                 \
        : "+f"(d[0]), "+f"(d[1]), "+f"(d[2]), "+f"(d[3])                       \
        : "r"(a[0]), "r"(a[1]), "r"(a[2]), "r"(a[3]), "r"(b[0]), "r"(b[1]))

// ---------------- fp16 GEMM: ldmatrix fragments, templated BK --------------
// A half row-major MxK. B half: KxN (NN, ldmatrix.trans) or NxK (NT).
// mode 0: C(float) = alpha*acc
// mode 1: C(half) scores epilogue + causal row sums into p3; masked tiles skip
// mode 2: C(float) = acc * p1[m]; Kend = tileM+128
#define BM 128
#define BN 128
#define BSTRH 136    // halves per NN-B row

template <int TBK>
__global__ __launch_bounds__(256)
void tgemm_kernel(int M, int N, int K,
                  const __half* __restrict__ A, int lda, long long sAb, long long sAn,
                  const __half* __restrict__ B, int ldb, long long sBb, long long sBn,
                  void* __restrict__ Cv, int ldc, long long sCb, long long sCn,
                  int nhd, int transB, int mode, float alpha,
                  const float* __restrict__ p1, const float* __restrict__ p2,
                  float* __restrict__ p3, int pstr)
{
    constexpr int ASTR   = TBK + 8;        // halves per A/NT-B smem row
    constexpr int CPR    = TBK / 8;        // 16B chunks per A row
    constexpr int PASSES = TBK / 16;       // loader passes (256 thr each)
    constexpr int RSH    = (CPR == 4) ? 2 : 3;
    constexpr int RSTEP  = 256 / CPR;

    const int z  = blockIdx.z;
    const int zb = z / nhd, zn = z % nhd;
    A += zb * sAb + zn * sAn;
    B += zb * sBb + zn * sBn;

    const int tileM = blockIdx.y * BM;
    const int tileN = blockIdx.x * BN;
    if (mode == 1 && tileN > tileM + BM - 1) return;

    const int t    = threadIdx.x;
    const int lane = t & 31;
    const int warp = t >> 5;
    const int g    = lane >> 2;
    const int t4   = lane & 3;
    const int wm   = (warp & 1) * 64;
    const int wn   = (warp >> 1) * 32;

    extern __shared__ __half sm[];
    __half* Asm[2] = { sm, sm + BM * ASTR };
    __half* Bsm[2] = { sm + 2 * BM * ASTR, sm + 3 * BM * ASTR };
    uint32_t sA[2], sB[2];
    sA[0] = (uint32_t)__cvta_generic_to_shared(Asm[0]);
    sA[1] = (uint32_t)__cvta_generic_to_shared(Asm[1]);
    sB[0] = (uint32_t)__cvta_generic_to_shared(Bsm[0]);
    sB[1] = (uint32_t)__cvta_generic_to_shared(Bsm[1]);

    float acc[4][4][4];
#pragma unroll
    for (int i = 0; i < 4; i++)
#pragma unroll
        for (int j = 0; j < 4; j++)
#pragma unroll
            for (int r = 0; r < 4; r++) acc[i][j][r] = 0.f;

    int Kend = K;
    if (mode == 2) { int lim = tileM + BM; Kend = lim < K ? lim : K; }
    const int nIter = Kend / TBK;

    // ---- precomputed loader state (pointers advance by constants) ----
    const int rowA = t >> RSH;
    const int kcA  = (t & (CPR - 1)) * 8;
    const __half* aP[PASSES];
    uint32_t aD[2][PASSES];
    const __half* bP[PASSES];
    uint32_t bD[2][PASSES];
    int bBytes = 16;

#pragma unroll
    for (int hh = 0; hh < PASSES; hh++) {
        int row = rowA + hh * RSTEP;
        aP[hh] = A + (long long)(tileM + row) * lda + kcA;
        aD[0][hh] = sA[0] + (row * ASTR + kcA) * 2;
        aD[1][hh] = sA[1] + (row * ASTR + kcA) * 2;
    }
    if (!transB) {
        int n8 = (t & 15) * 8;
        int gn = tileN + n8;
        bBytes = (gn < N) ? 16 : 0;
#pragma unroll
        for (int hh = 0; hh < PASSES; hh++) {
            int kr = (t >> 4) + 16 * hh;
            bP[hh] = B + (long long)kr * ldb + ((gn < N) ? gn : 0);
            bD[0][hh] = sB[0] + (kr * BSTRH + n8) * 2;
            bD[1][hh] = sB[1] + (kr * BSTRH + n8) * 2;
        }
    } else {
#pragma unroll
        for (int hh = 0; hh < PASSES; hh++) {
            int row = rowA + hh * RSTEP;
            bP[hh] = B + (long long)(tileN + row) * ldb + kcA;
            bD[0][hh] = sB[0] + (row * ASTR + kcA) * 2;
            bD[1][hh] = sB[1] + (row * ASTR + kcA) * 2;
        }
    }
    const int bAdv = transB ? TBK : TBK * ldb;

    auto loadTiles = [&](int stg) {
#pragma unroll
        for (int hh = 0; hh < PASSES; hh++) {
            cp16(aD[stg][hh], aP[hh], 16);
            aP[hh] += TBK;
        }
#pragma unroll
        for (int hh = 0; hh < PASSES; hh++) {
            cp16(bD[stg][hh], bP[hh], bBytes);
            bP[hh] += bAdv;
        }
        cp_commit();
    };

    // ldmatrix per-lane offsets (bytes)
    const uint32_t aOff = (uint32_t)(((wm + ((lane >> 3) & 1) * 8 + (lane & 7)) * ASTR
                                      + (lane >> 4) * 8) * 2);
    const uint32_t bOffNT = (uint32_t)(((wn + ((lane >> 4) & 1) * 8 + (lane & 7)) * ASTR
                                        + ((lane >> 3) & 1) * 8) * 2);
    const uint32_t bOffNN = (uint32_t)(((((lane >> 3) & 1) * 8 + (lane & 7)) * BSTRH
                                        + wn + ((lane >> 4) & 1) * 8) * 2);

    loadTiles(0);
    cp_wait0();
    __syncthreads();

    for (int it = 0; it < nIter; it++) {
        const int s = it & 1;
        const bool more = (it + 1 < nIter);
        if (more) loadTiles(s ^ 1);

        const uint32_t aBase = sA[s];
        const uint32_t bBase = sB[s];

#pragma unroll
        for (int ks = 0; ks < TBK; ks += 16) {
            uint32_t af[4][4], bf[4][2];
#pragma unroll
            for (int i = 0; i < 4; i++)
                ldsm4(af[i][0], af[i][1], af[i][2], af[i][3],
                      aBase + aOff + (uint32_t)((i * 16 * ASTR + ks) * 2));
            if (transB) {
#pragma unroll
                for (int jj = 0; jj < 4; jj += 2)
                    ldsm4(bf[jj][0], bf[jj][1], bf[jj + 1][0], bf[jj + 1][1],
                          bBase + bOffNT + (uint32_t)((jj * 8 * ASTR + ks) * 2));
            } else {
#pragma unroll
                for (int jj = 0; jj < 4; jj += 2)
                    ldsm4t(bf[jj][0], bf[jj][1], bf[jj + 1][0], bf[jj + 1][1],
                           bBase + bOffNN + (uint32_t)((ks * BSTRH + jj * 8) * 2));
            }
#pragma unroll
            for (int i = 0; i < 4; i++)
#pragma unroll
                for (int j = 0; j < 4; j++)
                    MMA_F16(acc[i][j], af[i], bf[j]);
        }

        if (more) cp_wait0();
        __syncthreads();
    }

    // ---- epilogue ----
    const long long zoff = (long long)z * pstr;
    float* Cf  = (float*)Cv;
    __half* Ch = (__half*)Cv;
    if (mode == 1) Ch += zb * sCb + zn * sCn;
    else           Cf += zb * sCb + zn * sCn;

    float p1v[8];
    if (mode == 1) {
#pragma unroll
        for (int j = 0; j < 4; j++) {
            int gn = tileN + wn + j * 8 + t4 * 2;
            p1v[2 * j]     = p1[zoff + gn];
            p1v[2 * j + 1] = p1[zoff + gn + 1];
        }
    }
#pragma unroll
    for (int i = 0; i < 4; i++) {
        int gmBase = tileM + wm + i * 16 + g;
#pragma unroll
        for (int half = 0; half < 2; half++) {
            int gm = gmBase + half * 8;
            float pmv = 0.f, rsv = 1.f;
            if (mode == 1)      pmv = p2[zoff + gm];
            else if (mode == 2) rsv = p1[zoff + gm];
            float rsum = 0.f;
#pragma unroll
            for (int j = 0; j < 4; j++) {
                int gn = tileN + wn + j * 8 + t4 * 2;
                if (gn >= N) continue;
                float v0 = acc[i][j][half * 2 + 0];
                float v1 = acc[i][j][half * 2 + 1];
                if (mode == 1) {
                    v0 = (gn     <= gm) ? v0 * alpha * __expf(p1v[2 * j    ] - pmv) : 0.f;
                    v1 = (gn + 1 <= gm) ? v1 * alpha * __expf(p1v[2 * j + 1] - pmv) : 0.f;
                    rsum += v0 + v1;
                    __half2 hv = __floats2half2_rn(v0, v1);
                    *reinterpret_cast<__half2*>(&Ch[(long long)gm * ldc + gn]) = hv;
                } else if (mode == 2) {
                    v0 *= rsv; v1 *= rsv;
                    *reinterpret_cast<float2*>(&Cf[(long long)gm * ldc + gn]) = make_float2(v0, v1);
                } else {
                    v0 *= alpha; v1 *= alpha;
                    *reinterpret_cast<float2*>(&Cf[(long long)gm * ldc + gn]) = make_float2(v0, v1);
                }
            }
            if (mode == 1) {
                rsum += __shfl_xor_sync(0xffffffffu, rsum, 1);
                rsum += __shfl_xor_sync(0xffffffffu, rsum, 2);
                if (t4 == 0) atomicAdd(&p3[zoff + gm], rsum);
            }
        }
    }
}

constexpr int SMEM32 = 4 * BM * (32 + 8) * 2;   // 40960 B
constexpr int SMEM64 = 4 * BM * (64 + 8) * 2;   // 73728 B

// ---------------- fp32 -> fp16 convert ----------------
__global__ void cvth_kernel(const float* __restrict__ in, __half* __restrict__ out,
                            long long n)
{
    long long i = ((long long)blockIdx.x * blockDim.x + threadIdx.x) * 8;
    if (i >= n) return;
    float4 a = *reinterpret_cast<const float4*>(in + i);
    float4 b = *reinterpret_cast<const float4*>(in + i + 4);
    __half2 h0 = __floats2half2_rn(a.x, a.y);
    __half2 h1 = __floats2half2_rn(a.z, a.w);
    __half2 h2 = __floats2half2_rn(b.x, b.y);
    __half2 h3 = __floats2half2_rn(b.z, b.w);
    uint2 pk0 = make_uint2(*reinterpret_cast<uint32_t*>(&h0), *reinterpret_cast<uint32_t*>(&h1));
    uint2 pk1 = make_uint2(*reinterpret_cast<uint32_t*>(&h2), *reinterpret_cast<uint32_t*>(&h3));
    *reinterpret_cast<uint2*>(out + i)     = pk0;
    *reinterpret_cast<uint2*>(out + i + 4) = pk1;
}

// ---------------- fused depthwise conv + SiLU + headwise q/k/v -------------
__global__ void convhead_kernel(const float* __restrict__ xmz,
                                const float* __restrict__ w,
                                const float* __restrict__ bias,
                                const float* __restrict__ Wq,
                                const float* __restrict__ Wk,
                                const float* __restrict__ Wv,
                                float* __restrict__ xca,
                                __half* __restrict__ qh,
                                __half* __restrict__ kh,
                                __half* __restrict__ vh)
{
    long long idx = (long long)blockIdx.x * blockDim.x + threadIdx.x;
    long long total = cBS * (long long)cNPH;
    if (idx >= total) return;
    int p = (int)(idx % cNPH);
    long long bs = idx / cNPH;
    int s = (int)(bs % cS);
    int col = p * 4;

    float4 xr[cKS];
#pragma unroll
    for (int tt = 0; tt < cKS; tt++) {
        int sp = s - (cKS - 1) + tt;
        if (sp >= 0)
            xr[tt] = *reinterpret_cast<const float4*>(xmz + (bs - (cKS - 1) + tt) * c2H + col);
        else
            xr[tt] = make_float4(0.f, 0.f, 0.f, 0.f);
    }
    float4 wt[cKS];
#pragma unroll
    for (int tt = 0; tt < cKS; tt++)
        wt[tt] = *reinterpret_cast<const float4*>(w + tt * cH + col);
    float4 bb = *reinterpret_cast<const float4*>(bias + col);

    float4 xc;
    xc.x = bb.x + xr[0].x*wt[0].x + xr[1].x*wt[1].x + xr[2].x*wt[2].x + xr[3].x*wt[3].x;
    xc.y = bb.y + xr[0].y*wt[0].y + xr[1].y*wt[1].y + xr[2].y*wt[2].y + xr[3].y*wt[3].y;
    xc.z = bb.z + xr[0].z*wt[0].z + xr[1].z*wt[1].z + xr[2].z*wt[2].z + xr[3].z*wt[3].z;
    xc.w = bb.w + xr[0].w*wt[0].w + xr[1].w*wt[1].w + xr[2].w*wt[2].w + xr[3].w*wt[3].w;
    xc.x = xc.x / (1.f + __expf(-xc.x));
    xc.y = xc.y / (1.f + __expf(-xc.y));
    xc.z = xc.z / (1.f + __expf(-xc.z));
    xc.w = xc.w / (1.f + __expf(-xc.w));

    long long base = bs * cH + col;
    *reinterpret_cast<float4*>(xca + base) = xc;

    float4 xv = xr[cKS - 1];

    const float4* wq4 = reinterpret_cast<const float4*>(Wq + p * 16);
    const float4* wk4 = reinterpret_cast<const float4*>(Wk + p * 16);
    const float4* wv4 = reinterpret_cast<const float4*>(Wv + p * 16);
    float4 q0 = wq4[0], q1 = wq4[1], q2 = wq4[2], q3 = wq4[3];
    float4 k0 = wk4[0], k1 = wk4[1], k2 = wk4[2], k3 = wk4[3];
    float4 v0 = wv4[0], v1 = wv4[1], v2 = wv4[2], v3 = wv4[3];
    float4 qo, ko, vo;
    qo.x = xc.x*q0.x + xc.y*q1.x + xc.z*q2.x + xc.w*q3.x;
    qo.y = xc.x*q0.y + xc.y*q1.y + xc.z*q2.y + xc.w*q3.y;
    qo.z = xc.x*q0.z + xc.y*q1.z + xc.z*q2.z + xc.w*q3.z;
    qo.w = xc.x*q0.w + xc.y*q1.w + xc.z*q2.w + xc.w*q3.w;
    ko.x = xc.x*k0.x + xc.y*k1.x + xc.z*k2.x + xc.w*k3.x;
    ko.y = xc.x*k0.y + xc.y*k1.y + xc.z*k2.y + xc.w*k3.y;
    ko.z = xc.x*k0.z + xc.y*k1.z + xc.z*k2.z + xc.w*k3.z;
    ko.w = xc.x*k0.w + xc.y*k1.w + xc.z*k2.w + xc.w*k3.w;
    vo.x = xv.x*v0.x + xv.y*v1.x + xv.z*v2.x + xv.w*v3.x;
    vo.y = xv.x*v0.y + xv.y*v1.y + xv.z*v2.y + xv.w*v3.y;
    vo.z = xv.x*v0.z + xv.y*v1.z + xv.z*v2.z + xv.w*v3.z;
    vo.w = xv.x*v0.w + xv.y*v1.w + xv.z*v2.w + xv.w*v3.w;

    __half2 qh0 = __floats2half2_rn(qo.x, qo.y), qh1 = __floats2half2_rn(qo.z, qo.w);
    __half2 kh0 = __floats2half2_rn(ko.x, ko.y), kh1 = __floats2half2_rn(ko.z, ko.w);
    __half2 vh0 = __floats2half2_rn(vo.x, vo.y), vh1 = __floats2half2_rn(vo.z, vo.w);
    *reinterpret_cast<uint2*>(qh + base) = make_uint2(*reinterpret_cast<uint32_t*>(&qh0),
                                                      *reinterpret_cast<uint32_t*>(&qh1));
    *reinterpret_cast<uint2*>(kh + base) = make_uint2(*reinterpret_cast<uint32_t*>(&kh0),
                                                      *reinterpret_cast<uint32_t*>(&kh1));
    *reinterpret_cast<uint2*>(vh + base) = make_uint2(*reinterpret_cast<uint32_t*>(&vh0),
                                                      *reinterpret_cast<uint32_t*>(&vh1));
}

// ---------------- gates (reads half q/k/v) ----------------
__global__ __launch_bounds__(256)
void gates_kernel(const __half* __restrict__ q, const __half* __restrict__ k,
                  const __half* __restrict__ v,
                  const float* __restrict__ Wig, const float* __restrict__ big,
                  const float* __restrict__ Wfg, const float* __restrict__ bfg,
                  float* __restrict__ ipre, float* __restrict__ fpre)
{
    const int warp = threadIdx.x >> 5;
    const int lane = threadIdx.x & 31;
    const int rw   = warp >> 1;
    const int half = warp & 1;
    const long long row = (long long)blockIdx.x * 4 + rw;

    float ai[4] = {0, 0, 0, 0}, af[4] = {0, 0, 0, 0};
    const int rbeg = half * cHALF;
    const int rend = rbeg + cHALF;
    const long long rbase = row * cH;

    for (int r = rbeg + lane; r < rend; r += 32) {
        float4 wi = *reinterpret_cast<const float4*>(Wig + (long long)r * 4);
        float4 wf = *reinterpret_cast<const float4*>(Wfg + (long long)r * 4);
        float val;
        if (r < cH)          val = __half2float(q[rbase + r]);
        else if (r < 2 * cH) val = __half2float(k[rbase + r - cH]);
        else                 val = __half2float(v[rbase + r - 2 * cH]);
        ai[0] += val * wi.x; ai[1] += val * wi.y;
        ai[2] += val * wi.z; ai[3] += val * wi.w;
        af[0] += val * wf.x; af[1] += val * wf.y;
        af[2] += val * wf.z; af[3] += val * wf.w;
    }

#pragma unroll
    for (int o = 16; o > 0; o >>= 1) {
#pragma unroll
        for (int n = 0; n < 4; n++) {
            ai[n] += __shfl_xor_sync(0xffffffffu, ai[n], o);
            af[n] += __shfl_xor_sync(0xffffffffu, af[n], o);
        }
    }

    __shared__ float part[4][8];
    if (half == 1 && lane == 0) {
#pragma unroll
        for (int n = 0; n < 4; n++) { part[rw][n] = ai[n]; part[rw][4 + n] = af[n]; }
    }
    __syncthreads();
    if (half == 0 && lane == 0) {
        int b = (int)(row / cS), s = (int)(row % cS);
#pragma unroll
        for (int n = 0; n < 4; n++) {
            ipre[(long long)(b * cNH + n) * cS + s] = ai[n] + part[rw][n]     + big[n];
            fpre[(long long)(b * cNH + n) * cS + s] = af[n] + part[rw][4 + n] + bfg[n];
        }
    }
}

// ---------------- scan ----------------
__global__ __launch_bounds__(256)
void scan_kernel(const float* __restrict__ ipre, const float* __restrict__ fpre,
                 float* __restrict__ cs, float* __restrict__ aArr,
                 float* __restrict__ pm, float* __restrict__ nsum)
{
    int bh = blockIdx.x;
    int t  = threadIdx.x;
    const float* fp = fpre + (long long)bh * cS;
    const float* ip = ipre + (long long)bh * cS;

    float loc[8];
    float sum = 0.f;
#pragma unroll
    for (int u = 0; u < 8; u++) {
        int j = t * 8 + u;
        float f = fp[j];
        float lf = fminf(f, 0.f) - log1pf(expf(-fabsf(f)));
        sum += lf;
        loc[u] = sum;
    }
    __shared__ float part[256];
    part[t] = sum;
    __syncthreads();
    for (int off = 1; off < 256; off <<= 1) {
        float vv = (t >= off) ? part[t - off] : 0.f;
        __syncthreads();
        part[t] += vv;
        __syncthreads();
    }
    float excl = part[t] - sum;

    float lmax[8];
    float amax = -1e30f;
#pragma unroll
    for (int u = 0; u < 8; u++) {
        int j = t * 8 + u;
        float csj = excl + loc[u];
        cs[(long long)bh * cS + j] = csj;
        float aj = ip[j] - csj;
        aArr[(long long)bh * cS + j] = aj;
        nsum[(long long)bh * cS + j] = 0.f;
        amax = fmaxf(amax, aj);
        lmax[u] = amax;
    }
    __syncthreads();
    part[t] = amax;
    __syncthreads();
    for (int off = 1; off < 256; off <<= 1) {
        float vv = (t >= off) ? part[t - off] : -1e30f;
        __syncthreads();
        part[t] = fmaxf(part[t], vv);
        __syncthreads();
    }
    float exmax = (t > 0) ? part[t - 1] : -1e30f;
#pragma unroll
    for (int u = 0; u < 8; u++) {
        int j = t * 8 + u;
        pm[(long long)bh * cS + j] = fmaxf(exmax, lmax[u]);
    }
}

// ---------------- finalize n -> rs ----------------
__global__ void nfin_kernel(const float* __restrict__ nsum,
                            const float* __restrict__ cs, const float* __restrict__ pm,
                            float* __restrict__ rs)
{
    int idx = blockIdx.x * blockDim.x + threadIdx.x;
    if (idx >= cBHS) return;
    float m = cs[idx] + pm[idx];
    float n = fmaxf(fabsf(nsum[idx]), __expf(-m));
    rs[idx] = 1.f / (n + 1e-6f);
}

// ---------------- multi-head LN + skip + z-gate (writes half hs) -----------
__global__ __launch_bounds__(256)
void ln_kernel(const float* __restrict__ hbuf, const float* __restrict__ xca,
               const float* __restrict__ xmz, const float* __restrict__ norm_w,
               const float* __restrict__ skip, __half* __restrict__ hsH)
{
    int s  = blockIdx.x;
    int bh = blockIdx.y;
    int t  = threadIdx.x;
    int b = bh / cNH, n = bh % cNH;
    const float* hrow = hbuf + ((long long)bh * cS + s) * cDH;

    float sum = 0.f, ss = 0.f;
    for (int d = t; d < cDH; d += 256) {
        float v = hrow[d];
        sum += v; ss += v * v;
    }
    __shared__ float r1[256], r2[256];
    r1[t] = sum; r2[t] = ss;
    __syncthreads();
    for (int o = 128; o > 0; o >>= 1) {
        if (t < o) { r1[t] += r1[t + o]; r2[t] += r2[t + o]; }
        __syncthreads();
    }
    float mean = r1[0] / cDH;
    float var  = r2[0] / cDH - mean * mean;
    float inv  = rsqrtf(var + 1e-5f);

    long long bsRow = (long long)b * cS + s;
    long long xbase = bsRow * cH;
    long long zbase = bsRow * c2H + cH;
    for (int d = t; d < cDH; d += 256) {
        int col = n * cDH + d;
        float hn = (hrow[d] - mean) * inv * norm_w[col];
        float hk = hn + skip[col] * xca[xbase + col];
        float zv = xmz[zbase + col];
        float sz = zv / (1.f + __expf(-zv));
        hsH[xbase + col] = __float2half(hk * sz);
    }
}

// ---------------- launch ----------------
extern "C" void kernel_launch(void* const* d_in, const int* in_sizes, int n_in,
                              void* d_out, int out_size)
{
    const float* x      = (const float*)d_in[0];
    const float* W_in   = (const float*)d_in[1];
    const float* conv_w = (const float*)d_in[2];
    const float* conv_b = (const float*)d_in[3];
    const float* Wq     = (const float*)d_in[4];
    const float* Wk     = (const float*)d_in[5];
    const float* Wv     = (const float*)d_in[6];
    const float* W_ig   = (const float*)d_in[7];
    const float* b_ig   = (const float*)d_in[8];
    const float* W_fg   = (const float*)d_in[9];
    const float* b_fg   = (const float*)d_in[10];
    const float* norm_w = (const float*)d_in[11];
    const float* skip   = (const float*)d_in[12];
    const float* W_out  = (const float*)d_in[13];
    float* out = (float*)d_out;

    float *p_xmz, *p_xca, *p_h;
    float *p_ipre, *p_fpre, *p_cs, *p_a, *p_pm, *p_rs, *p_ns;
    __half *p_xh, *p_WinH, *p_WoutH, *p_qh, *p_kh, *p_vh, *p_hsH, *p_scH;
    cudaGetSymbolAddress((void**)&p_xmz, g_xmz);
    cudaGetSymbolAddress((void**)&p_xca, g_xca);
    cudaGetSymbolAddress((void**)&p_h,   g_h);
    cudaGetSymbolAddress((void**)&p_xh,  g_xh);
    cudaGetSymbolAddress((void**)&p_WinH, g_WinH);
    cudaGetSymbolAddress((void**)&p_WoutH, g_WoutH);
    cudaGetSymbolAddress((void**)&p_qh,  g_qh);
    cudaGetSymbolAddress((void**)&p_kh,  g_kh);
    cudaGetSymbolAddress((void**)&p_vh,  g_vh);
    cudaGetSymbolAddress((void**)&p_hsH, g_hsH);
    cudaGetSymbolAddress((void**)&p_scH, g_scoresH);
    cudaGetSymbolAddress((void**)&p_ipre, g_ipre);
    cudaGetSymbolAddress((void**)&p_fpre, g_fpre);
    cudaGetSymbolAddress((void**)&p_cs,  g_cs);
    cudaGetSymbolAddress((void**)&p_a,   g_a);
    cudaGetSymbolAddress((void**)&p_pm,  g_pm);
    cudaGetSymbolAddress((void**)&p_rs,  g_rs);
    cudaGetSymbolAddress((void**)&p_ns,  g_nsum);

    cudaFuncSetAttribute(tgemm_kernel<64>, cudaFuncAttributeMaxDynamicSharedMemorySize, SMEM64);
    cudaFuncSetAttribute(tgemm_kernel<32>, cudaFuncAttributeMaxDynamicSharedMemorySize, SMEM32);

    const int M0 = (int)cBS;  // 4096

    // 0) fp16 conversions: x, W_in, W_out
    {
        long long nx = cBS * (long long)cE;
        cvth_kernel<<<(int)((nx / 8 + 255) / 256), 256>>>(x, p_xh, nx);
        long long nw = (long long)cE * c2H;
        cvth_kernel<<<(int)((nw / 8 + 255) / 256), 256>>>(W_in, p_WinH, nw);
        long long no = (long long)cH * cE;
        cvth_kernel<<<(int)((no / 8 + 255) / 256), 256>>>(W_out, p_WoutH, no);
    }

    // 1) xh @ WinH -> xmz (fp32 out, merged N = 2H)
    {
        dim3 grid(c2H / BN, M0 / BM, 1);
        tgemm_kernel<64><<<grid, 256, SMEM64>>>(M0, c2H, cE,
            p_xh, cE, 0, 0,
            p_WinH, c2H, 0, 0,
            p_xmz, c2H, 0, 0,
            1, 0, 0, 1.0f, nullptr, nullptr, nullptr, 0);
    }

    // 2+3) fused conv + SiLU + headwise -> xca fp32, q/k/v fp16
    {
        long long total = cBS * (long long)cNPH;
        int blocks = (int)((total + 255) / 256);
        convhead_kernel<<<blocks, 256>>>(p_xmz, conv_w, conv_b, Wq, Wk, Wv,
                                         p_xca, p_qh, p_kh, p_vh);
    }

    // 4) gates
    gates_kernel<<<M0 / 4, 256>>>(p_qh, p_kh, p_vh, W_ig, b_ig, W_fg, b_fg, p_ipre, p_fpre);

    // 5) scan (also zeroes nsum)
    scan_kernel<<<cB * cNH, 256>>>(p_ipre, p_fpre, p_cs, p_a, p_pm, p_ns);

    // 6) scores (mode 1, K=672 -> BK=32 instance)
    {
        dim3 grid(cS / BN, cS / BM, cB * cNH);
        float alpha = 1.0f / sqrtf((float)cDH);
        tgemm_kernel<32><<<grid, 256, SMEM32>>>(cS, cS, cDH,
            p_qh, cH, (long long)cS * cH, (long long)cDH,
            p_kh, cH, (long long)cS * cH, (long long)cDH,
            p_scH, cS, (long long)cNH * cS * cS, (long long)cS * cS,
            cNH, 1, 1, alpha, p_a, p_pm, p_ns, cS);
    }

    // 7) finalize rs
    nfin_kernel<<<(cBHS + 255) / 256, 256>>>(p_ns, p_cs, p_pm, p_rs);

    // 8) h = diag(rs) * scoresH @ vh (mode 2, K=2048 -> BK=64)
    {
        dim3 grid((cDH + BN - 1) / BN, cS / BM, cB * cNH);
        tgemm_kernel<64><<<grid, 256, SMEM64>>>(cS, cDH, cS,
            p_scH, cS, (long long)cNH * cS * cS, (long long)cS * cS,
            p_vh, cH, (long long)cS * cH, (long long)cDH,
            p_h, cDH, (long long)cNH * cS * cDH, (long long)cS * cDH,
            cNH, 0, 2, 1.0f, p_rs, nullptr, nullptr, cS);
    }

    // 9) LN + skip + z gate -> hs fp16
    {
        dim3 grid(cS, cB * cNH);
        ln_kernel<<<grid, 256>>>(p_h, p_xca, p_xmz, norm_w, skip, p_hsH);
    }

    // 10) out = hsH @ WoutH (fp32 out, K=2688 -> BK=64)
    {
        dim3 grid(cE / BN, M0 / BM, 1);
        tgemm_kernel<64><<<grid, 256, SMEM64>>>(M0, cE, cH,
            p_hsH, cH, 0, 0,
            p_WoutH, cE, 0, 0,
            out, cE, 0, 0,
            1, 0, 0, 1.0f, nullptr, nullptr, nullptr, 0);
    }
}